// round 6
// baseline (speedup 1.0000x reference)
#include <cuda_runtime.h>
#include <math.h>

#define SS 512
#define NROWS 32768LL

// ------------------- device scratch (no allocs allowed) -------------------
__device__ float d_embs[32768*360];
__device__ float d_Xf[32768*1024];
__device__ float d_Xb[32768*1024];
__device__ float d_q[32768*512];
__device__ float d_k[32768*512];
__device__ float d_scores[67108864];
__device__ float d_adjens[16777216];
__device__ float d_tb[16777216];
__device__ float d_x1[8388608];
__device__ float d_denom[32768];
__device__ float d_thre[64];
__device__ float d_biasf[1024];
__device__ float d_biasb[1024];
__device__ float4 d_hx4[2*16*512];
__device__ unsigned d_barc[16];

// ------------------- small prep kernels -------------------
__global__ void prep_kernel(const float* bihf, const float* bhhf,
                            const float* bihb, const float* bhhb) {
    int i = blockIdx.x*blockDim.x + threadIdx.x;
    if (i < 1024) { d_biasf[i] = bihf[i]+bhhf[i]; d_biasb[i] = bihb[i]+bhhb[i]; }
}

__global__ void init_kernel() {
    int i = blockIdx.x*blockDim.x + threadIdx.x;
    if (i < 16) d_barc[i] = 0u;
    float4 z = make_float4(0.f,0.f,0.f,0.f);
    for (int j = i; j < 2*16*512; j += blockDim.x*gridDim.x) d_hx4[j] = z;
}

__global__ void embed_kernel(const int* __restrict__ tok, const int* __restrict__ pos,
                             const int* __restrict__ post, const float* __restrict__ emb,
                             const float* __restrict__ pose, const float* __restrict__ poste) {
    int r = blockIdx.x;
    int t = tok[r], p = pos[r], q = post[r];
    float* o = d_embs + (long long)r*360;
    for (int d = threadIdx.x; d < 360; d += blockDim.x) {
        float v;
        if (d < 300)      v = emb[(long long)t*300 + d];
        else if (d < 330) v = pose[p*30 + (d-300)];
        else              v = poste[q*30 + (d-330)];
        o[d] = v;
    }
}

#define COMPUTE_TILE(buf)                                               \
    _Pragma("unroll")                                                   \
    for (int kk = 0; kk < 8; kk++) {                                    \
        float av[8], bv[8];                                             \
        *(float4*)&av[0] = *(const float4*)&As[buf][kk][ty];            \
        *(float4*)&av[4] = *(const float4*)&As[buf][kk][ty+4];          \
        *(float4*)&bv[0] = *(const float4*)&Bs[buf][kk][tx];            \
        *(float4*)&bv[4] = *(const float4*)&Bs[buf][kk][tx+4];          \
        _Pragma("unroll")                                               \
        for (int i = 0; i < 8; i++)                                     \
            _Pragma("unroll")                                           \
            for (int j = 0; j < 8; j++)                                 \
                acc[i][j] = fmaf(av[i], bv[j], acc[i][j]);              \
    }

// ------------------- SGEMM NT (3-stage pipeline, conflict-free stores):
// C = alpha*A[M,K]@B[N,K]^T (+bias)(/denom)(relu), with optional length-skip.
__global__ __launch_bounds__(256,2) void sgemm_nt(
    const float* __restrict__ A, int lda, long long sAo, long long sAi,
    const float* __restrict__ B, int ldb, long long sBo, long long sBi,
    float* __restrict__ C, int ldc, long long sCo, long long sCi,
    int innerZ, int K, float alpha,
    const float* __restrict__ bias, const float* __restrict__ denom, int relu,
    const int* __restrict__ lens, int colskip)
{
    int z = blockIdx.z; int zo = z / innerZ; int zi = z - zo*innerZ;
    if (lens) {
        int rowg = blockIdx.y*128;
        int bsm = (innerZ > 1) ? zo : (rowg >> 9);
        int lb = lens[bsm];
        int rloc = (innerZ > 1) ? rowg : (rowg & 511);
        if (rloc >= lb) return;
        if (colskip && blockIdx.x*128 >= lb) return;
    }
    A += zo*sAo + zi*sAi; B += zo*sBo + zi*sBi; C += zo*sCo + zi*sCi;
    __shared__ float As[3][8][128];
    __shared__ float Bs[3][8][128];
    int tid = threadIdx.x;
    int r = tid & 127;
    const float* G = (tid < 128)
        ? (A + (long long)(blockIdx.y*128 + r)*lda)
        : (B + (long long)(blockIdx.x*128 + r)*ldb);
    float (*S)[8][128] = (tid < 128) ? As : Bs;

    float acc[8][8];
#pragma unroll
    for (int i = 0; i < 8; i++)
#pragma unroll
        for (int j = 0; j < 8; j++) acc[i][j] = 0.f;
    int tx = (tid & 15) * 8;
    int ty = (tid >> 4) * 8;

    int KT = K >> 3;
    {
        float4 p0 = *(const float4*)(G + 0);
        float4 p1 = *(const float4*)(G + 4);
        S[0][0][r]=p0.x; S[0][1][r]=p0.y; S[0][2][r]=p0.z; S[0][3][r]=p0.w;
        S[0][4][r]=p1.x; S[0][5][r]=p1.y; S[0][6][r]=p1.z; S[0][7][r]=p1.w;
        p0 = *(const float4*)(G + 8);
        p1 = *(const float4*)(G + 12);
        S[1][0][r]=p0.x; S[1][1][r]=p0.y; S[1][2][r]=p0.z; S[1][3][r]=p0.w;
        S[1][4][r]=p1.x; S[1][5][r]=p1.y; S[1][6][r]=p1.z; S[1][7][r]=p1.w;
    }
    __syncthreads();
    int cur = 0;
    for (int kt = 2; kt < KT; kt++) {
        int k0 = kt << 3;
        float4 p0 = *(const float4*)(G + k0);
        float4 p1 = *(const float4*)(G + k0 + 4);
        COMPUTE_TILE(cur);
        int st = kt % 3;
        S[st][0][r]=p0.x; S[st][1][r]=p0.y; S[st][2][r]=p0.z; S[st][3][r]=p0.w;
        S[st][4][r]=p1.x; S[st][5][r]=p1.y; S[st][6][r]=p1.z; S[st][7][r]=p1.w;
        __syncthreads();
        cur++; if (cur == 3) cur = 0;
    }
    COMPUTE_TILE(cur);
    cur++; if (cur == 3) cur = 0;
    COMPUTE_TILE(cur);

    int rowBase = blockIdx.y*128 + ty;
    int colBase = blockIdx.x*128 + tx;
#pragma unroll
    for (int i = 0; i < 8; i++) {
        int row = rowBase + i;
        float rd = denom ? (1.0f/denom[row]) : 1.0f;
        float* crow = C + (long long)row*ldc + colBase;
#pragma unroll
        for (int j = 0; j < 8; j++) {
            float v = acc[i][j] * alpha;
            if (bias) v += bias[colBase + j];
            v *= rd;
            if (relu) v = fmaxf(v, 0.f);
            crow[j] = v;
        }
    }
}

// ------------------- SGEMM NN (batched, 3-stage): C = A[M,K]@B[K,N]
// lens: per-z sample length; skip row tiles >= l (C pre-zeroed) and clamp K.
__global__ __launch_bounds__(256,2) void sgemm_nn(
    const float* __restrict__ A, int lda, long long sA,
    const float* __restrict__ B, int ldb, long long sB,
    float* __restrict__ C, int ldc, long long sC, int K,
    const int* __restrict__ lens)
{
    int z = blockIdx.z;
    if (lens) {
        int lb = lens[z];
        if (blockIdx.y*128 >= lb) return;
        int Keff = ((lb + 7) >> 3) << 3;
        if (Keff < K) K = Keff;
    }
    A += (long long)z*sA; B += (long long)z*sB; C += (long long)z*sC;
    __shared__ float As[3][8][128];
    __shared__ float Bs[3][8][128];
    int tid = threadIdx.x;
    int r = tid & 127;

    const float* G;
    int kRow = 0, cB = 0;
    if (tid < 128) {
        G = A + (long long)(blockIdx.y*128 + r)*lda;
    } else {
        kRow = r >> 4; cB = (r & 15) * 8;
        G = B + (long long)kRow*ldb + blockIdx.x*128 + cB;
    }

    float acc[8][8];
#pragma unroll
    for (int i = 0; i < 8; i++)
#pragma unroll
        for (int j = 0; j < 8; j++) acc[i][j] = 0.f;
    int tx = (tid & 15) * 8;
    int ty = (tid >> 4) * 8;

    int KT = K >> 3;
    if (tid < 128) {
        float4 p0 = *(const float4*)(G + 0);
        float4 p1 = *(const float4*)(G + 4);
        As[0][0][r]=p0.x; As[0][1][r]=p0.y; As[0][2][r]=p0.z; As[0][3][r]=p0.w;
        As[0][4][r]=p1.x; As[0][5][r]=p1.y; As[0][6][r]=p1.z; As[0][7][r]=p1.w;
        p0 = *(const float4*)(G + 8);
        p1 = *(const float4*)(G + 12);
        As[1][0][r]=p0.x; As[1][1][r]=p0.y; As[1][2][r]=p0.z; As[1][3][r]=p0.w;
        As[1][4][r]=p1.x; As[1][5][r]=p1.y; As[1][6][r]=p1.z; As[1][7][r]=p1.w;
    } else {
        float4 p0 = *(const float4*)(G);
        float4 p1 = *(const float4*)(G + 4);
        *(float4*)&Bs[0][kRow][cB]   = p0;
        *(float4*)&Bs[0][kRow][cB+4] = p1;
        p0 = *(const float4*)(G + (long long)8*ldb);
        p1 = *(const float4*)(G + (long long)8*ldb + 4);
        *(float4*)&Bs[1][kRow][cB]   = p0;
        *(float4*)&Bs[1][kRow][cB+4] = p1;
    }
    __syncthreads();
    int cur = 0;
    for (int kt = 2; kt < KT; kt++) {
        int k0 = kt << 3;
        float4 p0, p1;
        if (tid < 128) {
            p0 = *(const float4*)(G + k0);
            p1 = *(const float4*)(G + k0 + 4);
        } else {
            p0 = *(const float4*)(G + (long long)k0*ldb);
            p1 = *(const float4*)(G + (long long)k0*ldb + 4);
        }
        COMPUTE_TILE(cur);
        int st = kt % 3;
        if (tid < 128) {
            As[st][0][r]=p0.x; As[st][1][r]=p0.y; As[st][2][r]=p0.z; As[st][3][r]=p0.w;
            As[st][4][r]=p1.x; As[st][5][r]=p1.y; As[st][6][r]=p1.z; As[st][7][r]=p1.w;
        } else {
            *(float4*)&Bs[st][kRow][cB]   = p0;
            *(float4*)&Bs[st][kRow][cB+4] = p1;
        }
        __syncthreads();
        cur++; if (cur == 3) cur = 0;
    }
    COMPUTE_TILE(cur);
    cur++; if (cur == 3) cur = 0;
    COMPUTE_TILE(cur);

    int rowBase = blockIdx.y*128 + ty;
    int colBase = blockIdx.x*128 + tx;
#pragma unroll
    for (int i = 0; i < 8; i++) {
        float* crow = C + (long long)(rowBase+i)*ldc + colBase;
#pragma unroll
        for (int j = 0; j < 8; j++) crow[j] = acc[i][j];
    }
}

// ------------------- BiLSTM recurrence: 4 samples/thread -------------------
// 128 blocks = 16 groups(8 samples x dir) x 8 j-split, 256 threads each.
// Each W float4 feeds 16 FMAs (was 8): W smem traffic halved vs R4.
__global__ __launch_bounds__(256) void lstm_kernel(
    const float* __restrict__ Whhf, const float* __restrict__ Whhb,
    const int* __restrict__ l, float* __restrict__ gout)
{
    extern __shared__ float sm[];
    float* Ws = sm;                 // 32768 floats, f4 layout [k4][128 rows]
    float* hs = sm + 32768;         // [8][256]
    float* gs = hs + 2048;          // [8][128]
    float* cs = gs + 1024;          // [8][32]
    int bid = blockIdx.x; int group = bid >> 3; int q = bid & 7;
    int dir = group >> 3; int sg = group & 7;
    int tid = threadIdx.x;
    const float* Whh = dir ? Whhb : Whhf;
    const float* Xd = dir ? d_Xb : d_Xf;
    for (int idx = tid; idx < 32768; idx += 256) {
        int rr = idx >> 8; int kk = idx & 255;
        int gr = ((rr>>5)<<8) + (q<<5) + (rr&31);
        Ws[(((kk>>2)*128)+rr)*4 + (kk&3)] = Whh[gr*256 + kk];
    }
    cs[tid] = 0.f;
    int ln[8]; int lmax = 0;
#pragma unroll
    for (int n = 0; n < 8; n++) { ln[n] = l[sg*8+n]; lmax = max(lmax, ln[n]); }
    int slot = tid >> 7; int r = tid & 127;
    int n0 = slot*4;                 // samples n0..n0+3
    int grow = ((r>>5)<<8) + (q<<5) + (r&31);
    __syncthreads();
    const float4* Ws4 = (const float4*)Ws;
    for (int t = 0; t < lmax; t++) {
        ((float4*)hs)[tid]     = __ldcg(&d_hx4[(t&1)*8192 + group*512 + tid]);
        ((float4*)hs)[tid+256] = __ldcg(&d_hx4[(t&1)*8192 + group*512 + tid + 256]);
        __syncthreads();
        float acc0 = 0.f, acc1 = 0.f, acc2 = 0.f, acc3 = 0.f;
        {
            int nA = n0+0, nB = n0+1, nC = n0+2, nD = n0+3;
            if (t < ln[nA]) { int tt = dir ? (ln[nA]-1-t) : t; acc0 = Xd[((long long)((sg*8+nA)*SS+tt)<<10) + grow]; }
            if (t < ln[nB]) { int tt = dir ? (ln[nB]-1-t) : t; acc1 = Xd[((long long)((sg*8+nB)*SS+tt)<<10) + grow]; }
            if (t < ln[nC]) { int tt = dir ? (ln[nC]-1-t) : t; acc2 = Xd[((long long)((sg*8+nC)*SS+tt)<<10) + grow]; }
            if (t < ln[nD]) { int tt = dir ? (ln[nD]-1-t) : t; acc3 = Xd[((long long)((sg*8+nD)*SS+tt)<<10) + grow]; }
        }
        const float4* h0 = (const float4*)(hs + (n0+0)*256);
        const float4* h1 = (const float4*)(hs + (n0+1)*256);
        const float4* h2 = (const float4*)(hs + (n0+2)*256);
        const float4* h3 = (const float4*)(hs + (n0+3)*256);
#pragma unroll 8
        for (int k4 = 0; k4 < 64; k4++) {
            float4 w = Ws4[k4*128 + r];
            float4 a = h0[k4], b = h1[k4], c = h2[k4], d = h3[k4];
            acc0 = fmaf(w.x,a.x, fmaf(w.y,a.y, fmaf(w.z,a.z, fmaf(w.w,a.w, acc0))));
            acc1 = fmaf(w.x,b.x, fmaf(w.y,b.y, fmaf(w.z,b.z, fmaf(w.w,b.w, acc1))));
            acc2 = fmaf(w.x,c.x, fmaf(w.y,c.y, fmaf(w.z,c.z, fmaf(w.w,c.w, acc2))));
            acc3 = fmaf(w.x,d.x, fmaf(w.y,d.y, fmaf(w.z,d.z, fmaf(w.w,d.w, acc3))));
        }
        gs[(n0+0)*128 + r] = acc0;
        gs[(n0+1)*128 + r] = acc1;
        gs[(n0+2)*128 + r] = acc2;
        gs[(n0+3)*128 + r] = acc3;
        __syncthreads();
        {
            int n = tid >> 5, jl = tid & 31;
            if (t < ln[n]) {
                float gi = gs[n*128+jl], gf = gs[n*128+32+jl];
                float gg = gs[n*128+64+jl], go_ = gs[n*128+96+jl];
                float c = cs[n*32+jl];
                c = (1.f/(1.f+expf(-gf)))*c + (1.f/(1.f+expf(-gi)))*tanhf(gg);
                float h = (1.f/(1.f+expf(-go_)))*tanhf(c);
                cs[n*32+jl] = c;
                float* dst = (float*)&d_hx4[((t+1)&1)*8192 + group*512];
                __stcg(dst + n*256 + q*32 + jl, h);
                int bsm = sg*8+n;
                int tpos = dir ? (ln[n]-1-t) : t;
                gout[((long long)(bsm*SS+tpos))*512 + dir*256 + q*32 + jl] = h;
            }
        }
        __threadfence();
        __syncthreads();
        if (tid == 0) {
            atomicAdd(&d_barc[group], 1u);
            unsigned tgt = (unsigned)(t+1)*8u;
            while (atomicAdd(&d_barc[group], 0u) < tgt) { }
        }
        __syncthreads();
    }
}

// ------------------- masked softmax + head mean + diag -------------------
__global__ void softmax_kernel(const int* __restrict__ l, float* __restrict__ ag) {
    int row = blockIdx.x; int b = row >> 9; int i = row & 511;
    int lb = l[b];
    float* out = ag + (long long)row*512;
    int tid = threadIdx.x;
    if (i >= lb) { out[tid] = 0.f; out[tid+256] = 0.f; return; }
    __shared__ float red[8];
    float a0 = 0.f, a1 = 0.f;
    int lane = tid & 31, wid = tid >> 5;
    for (int h = 0; h < 4; h++) {
        const float* sr = d_scores + ((long long)((b*4+h)*512 + i))*512;
        float v0 = (tid < lb)     ? sr[tid]     : -3.0e38f;
        float v1 = (tid+256 < lb) ? sr[tid+256] : -3.0e38f;
        float m = fmaxf(v0, v1);
        for (int o = 16; o; o >>= 1) m = fmaxf(m, __shfl_xor_sync(0xffffffffu, m, o));
        if (lane == 0) red[wid] = m;
        __syncthreads();
        m = red[0];
#pragma unroll
        for (int w = 1; w < 8; w++) m = fmaxf(m, red[w]);
        __syncthreads();
        float e0 = (tid < lb)     ? expf(v0 - m) : 0.f;
        float e1 = (tid+256 < lb) ? expf(v1 - m) : 0.f;
        float s = e0 + e1;
        for (int o = 16; o; o >>= 1) s += __shfl_xor_sync(0xffffffffu, s, o);
        if (lane == 0) red[wid] = s;
        __syncthreads();
        s = 0.f;
#pragma unroll
        for (int w = 0; w < 8; w++) s += red[w];
        float inv = 1.f/s;
        a0 += e0*inv; a1 += e1*inv;
        __syncthreads();
    }
    a0 *= 0.25f; a1 *= 0.25f;
    if (tid == i) a0 = 1.f;
    if (tid+256 == i) a1 = 1.f;
    out[tid] = a0; out[tid+256] = a1;
}

// ------------- exact kk-th smallest nonzero via 4-pass radix select ----------
__global__ __launch_bounds__(1024) void kth_kernel(const float* __restrict__ ag) {
    __shared__ unsigned wh[32][256];
    __shared__ unsigned chist[256];
    __shared__ int s_k, s_rem; __shared__ unsigned s_pref;
    int b = blockIdx.x; int tid = threadIdx.x; int wid = tid >> 5;
    const float* f = ag + (long long)b*262144;
    for (int pass = 0; pass < 4; pass++) {
        int shift = 24 - 8*pass;
        for (int j = tid; j < 32*256; j += 1024) ((unsigned*)wh)[j] = 0u;
        __syncthreads();
        unsigned pref = (pass == 0) ? 0u : s_pref;
        unsigned prefHi = pref >> (shift+8);
        for (int j = tid; j < 262144; j += 1024) {
            unsigned ub = __float_as_uint(f[j]);
            if (ub != 0u) {
                if (pass == 0 || (ub >> (shift+8)) == prefHi)
                    atomicAdd(&wh[wid][(ub >> shift) & 255u], 1u);
            }
        }
        __syncthreads();
        if (tid < 256) {
            unsigned s = 0;
#pragma unroll
            for (int w = 0; w < 32; w++) s += wh[w][tid];
            chist[tid] = s;
        }
        __syncthreads();
        if (tid == 0) {
            if (pass == 0) {
                unsigned nnz = 0;
                for (int c = 0; c < 256; c++) nnz += chist[c];
                int kk = (int)floorf((float)((int)nnz - 512) * 0.3f);
                s_k = kk; s_rem = kk; s_pref = 0u;
            }
            if (s_k > 0) {
                int rem = s_rem; unsigned pf = s_pref;
                for (int c = 0; c < 256; c++) {
                    if ((int)chist[c] >= rem) { pf |= ((unsigned)c) << shift; break; }
                    rem -= (int)chist[c];
                }
                s_rem = rem; s_pref = pf;
            }
        }
        __syncthreads();
        if (s_k <= 0) break;
    }
    if (tid == 0) d_thre[b] = (s_k > 0) ? __uint_as_float(s_pref) : 0.f;
}

// ------------------- prune + ensemble + denom -------------------
__global__ void prune_kernel(const float* __restrict__ adj, float* __restrict__ ag) {
    int row = blockIdx.x; int b = row >> 9; int tid = threadIdx.x;
    float thre = d_thre[b];
    long long base = (long long)row*512;
    float s = 0.f;
#pragma unroll
    for (int u = 0; u < 2; u++) {
        int j = tid + u*256;
        float v = ag[base + j];
        v = (v <= thre) ? 0.f : v;
        ag[base + j] = v;
        float e = 0.5f*adj[base + j] + 0.5f*v;
        d_adjens[base + j] = e;
        s += e;
    }
    for (int o = 16; o; o >>= 1) s += __shfl_xor_sync(0xffffffffu, s, o);
    __shared__ float red[8];
    if ((tid & 31) == 0) red[tid >> 5] = s;
    __syncthreads();
    if (tid == 0) {
        float tot = 0.f;
#pragma unroll
        for (int w = 0; w < 8; w++) tot += red[w];
        d_denom[row] = tot + 1.f;
    }
}

// ------------------- host launcher -------------------
extern "C" void kernel_launch(void* const* d_in, const int* in_sizes, int n_in,
                              void* d_out, int out_size) {
    const float* adj    = (const float*)d_in[0];
    const int*   tok    = (const int*)d_in[1];
    const int*   pos    = (const int*)d_in[2];
    const int*   post   = (const int*)d_in[3];
    const int*   l      = (const int*)d_in[4];
    const float* emb    = (const float*)d_in[5];
    const float* pose   = (const float*)d_in[6];
    const float* poste  = (const float*)d_in[7];
    const float* Wih_f  = (const float*)d_in[8];
    const float* Whh_f  = (const float*)d_in[9];
    const float* bih_f  = (const float*)d_in[10];
    const float* bhh_f  = (const float*)d_in[11];
    const float* Wih_b  = (const float*)d_in[12];
    const float* Whh_b  = (const float*)d_in[13];
    const float* bih_b  = (const float*)d_in[14];
    const float* bhh_b  = (const float*)d_in[15];
    const float* Wq     = (const float*)d_in[16];
    const float* bq     = (const float*)d_in[17];
    const float* Wk     = (const float*)d_in[18];
    const float* bk     = (const float*)d_in[19];
    const float* W0     = (const float*)d_in[20];
    const float* b0     = (const float*)d_in[21];
    const float* W1     = (const float*)d_in[22];
    const float* b1     = (const float*)d_in[23];

    float* xo = (float*)d_out;                      // [B,S,256]
    float* ag = xo + 8388608;                       // [B,S,S]
    float* go = xo + 25165824;                      // [B,S,512]

    void *pv;
    cudaGetSymbolAddress(&pv, d_embs);   float* embs   = (float*)pv;
    cudaGetSymbolAddress(&pv, d_Xf);     float* Xf     = (float*)pv;
    cudaGetSymbolAddress(&pv, d_Xb);     float* Xb     = (float*)pv;
    cudaGetSymbolAddress(&pv, d_q);      float* qb     = (float*)pv;
    cudaGetSymbolAddress(&pv, d_k);      float* kb     = (float*)pv;
    cudaGetSymbolAddress(&pv, d_scores); float* sc     = (float*)pv;
    cudaGetSymbolAddress(&pv, d_adjens); float* ens    = (float*)pv;
    cudaGetSymbolAddress(&pv, d_tb);     float* tbuf   = (float*)pv;
    cudaGetSymbolAddress(&pv, d_x1);     float* x1     = (float*)pv;
    cudaGetSymbolAddress(&pv, d_denom);  float* den    = (float*)pv;
    cudaGetSymbolAddress(&pv, d_biasf);  float* biasf  = (float*)pv;
    cudaGetSymbolAddress(&pv, d_biasb);  float* biasb  = (float*)pv;

    cudaMemsetAsync(go, 0, (size_t)NROWS*512*sizeof(float));
    prep_kernel<<<4,256>>>(bih_f, bhh_f, bih_b, bhh_b);
    init_kernel<<<16,1024>>>();
    embed_kernel<<<32768,128>>>(tok, pos, post, emb, pose, poste);

    // X = embs @ Wih^T + bias   [32768,1024]  (skip row tiles beyond l[b])
    sgemm_nt<<<dim3(8,256,1),256>>>(embs,360,0,0, Wih_f,360,0,0, Xf,1024,0,0,
                                    1,360,1.f, biasf, nullptr, 0, l, 0);
    sgemm_nt<<<dim3(8,256,1),256>>>(embs,360,0,0, Wih_b,360,0,0, Xb,1024,0,0,
                                    1,360,1.f, biasb, nullptr, 0, l, 0);

    cudaFuncSetAttribute(lstm_kernel, cudaFuncAttributeMaxDynamicSharedMemorySize, 36096*4);
    lstm_kernel<<<128,256,36096*4>>>(Whh_f, Whh_b, l, go);

    // q, k (skip row tiles beyond l[b])
    sgemm_nt<<<dim3(4,256,1),256>>>(go,512,0,0, Wq,512,0,0, qb,512,0,0,
                                    1,512,1.f, bq, nullptr, 0, l, 0);
    sgemm_nt<<<dim3(4,256,1),256>>>(go,512,0,0, Wk,512,0,0, kb,512,0,0,
                                    1,512,1.f, bk, nullptr, 0, l, 0);
    // scores[b,h] = q_bh @ k_bh^T / sqrt(128)  (skip row AND col tiles >= l[b])
    float alpha = 1.f/sqrtf(128.f);
    sgemm_nt<<<dim3(4,4,256),256>>>(qb,512, 262144,128, kb,512, 262144,128,
                                    sc,512, 1048576,262144, 4,128, alpha,
                                    nullptr, nullptr, 0, l, 1);
    softmax_kernel<<<32768,256>>>(l, ag);
    kth_kernel<<<64,1024>>>(ag);
    prune_kernel<<<32768,256>>>(adj, ag);

    // GCN layer 1: t = adjens @ g ; x1 = relu((t@W0^T+b0)/denom)
    cudaMemsetAsync(tbuf, 0, (size_t)16777216*sizeof(float));
    sgemm_nn<<<dim3(4,4,64),256>>>(ens,512,262144, go,512,262144, tbuf,512,262144, 512, l);
    sgemm_nt<<<dim3(2,256,1),256>>>(tbuf,512,0,0, W0,512,0,0, x1,256,0,0,
                                    1,512,1.f, b0, den, 1, nullptr, 0);
    // GCN layer 2: t2 = adjens @ x1 ; x = relu((t2@W1^T+b1)/denom)
    cudaMemsetAsync(tbuf, 0, (size_t)8388608*sizeof(float));
    sgemm_nn<<<dim3(2,4,64),256>>>(ens,512,262144, x1,256,131072, tbuf,256,131072, 512, l);
    sgemm_nt<<<dim3(2,256,1),256>>>(tbuf,256,0,0, W1,256,0,0, xo,256,0,0,
                                    1,256,1.f, b1, den, 1, nullptr, 0);
    (void)in_sizes; (void)n_in; (void)out_size;
}

// round 7
// speedup vs baseline: 1.0930x; 1.0930x over previous
#include <cuda_runtime.h>
#include <math.h>

#define SS 512
#define NROWS 32768LL

// ------------------- device scratch (no allocs allowed) -------------------
__device__ float d_embs[32768*360];
__device__ float d_Xf[32768*1024];
__device__ float d_Xb[32768*1024];
__device__ float d_q[32768*512];
__device__ float d_k[32768*512];
__device__ float d_scores[67108864];
__device__ float d_adjens[16777216];
__device__ float d_tb[16777216];
__device__ float d_x1[8388608];
__device__ float d_denom[32768];
__device__ float d_thre[64];
__device__ float d_biasf[1024];
__device__ float d_biasb[1024];
__device__ float4 d_hx4[2*16*512];
__device__ unsigned d_barc[16];
__device__ int d_perm[64];

// ------------------- small prep kernels -------------------
__global__ void prep_kernel(const float* bihf, const float* bhhf,
                            const float* bihb, const float* bhhb) {
    int i = blockIdx.x*blockDim.x + threadIdx.x;
    if (i < 1024) { d_biasf[i] = bihf[i]+bhhf[i]; d_biasb[i] = bihb[i]+bhhb[i]; }
}

__global__ void init_kernel() {
    int i = blockIdx.x*blockDim.x + threadIdx.x;
    if (i < 16) d_barc[i] = 0u;
    float4 z = make_float4(0.f,0.f,0.f,0.f);
    for (int j = i; j < 2*16*512; j += blockDim.x*gridDim.x) d_hx4[j] = z;
}

// rank-sort 64 lengths ascending -> d_perm (stable)
__global__ void sort_kernel(const int* __restrict__ l) {
    int i = threadIdx.x;
    int li = l[i]; int r = 0;
    for (int j = 0; j < 64; j++) {
        int lj = l[j];
        r += (lj < li) || (lj == li && j < i);
    }
    d_perm[r] = i;
}

__global__ void embed_kernel(const int* __restrict__ tok, const int* __restrict__ pos,
                             const int* __restrict__ post, const float* __restrict__ emb,
                             const float* __restrict__ pose, const float* __restrict__ poste) {
    int r = blockIdx.x;
    int t = tok[r], p = pos[r], q = post[r];
    float* o = d_embs + (long long)r*360;
    for (int d = threadIdx.x; d < 360; d += blockDim.x) {
        float v;
        if (d < 300)      v = emb[(long long)t*300 + d];
        else if (d < 330) v = pose[p*30 + (d-300)];
        else              v = poste[q*30 + (d-330)];
        o[d] = v;
    }
}

#define COMPUTE_TILE(buf)                                               \
    _Pragma("unroll")                                                   \
    for (int kk = 0; kk < 8; kk++) {                                    \
        float av[8], bv[8];                                             \
        *(float4*)&av[0] = *(const float4*)&As[buf][kk][ty];            \
        *(float4*)&av[4] = *(const float4*)&As[buf][kk][ty+4];          \
        *(float4*)&bv[0] = *(const float4*)&Bs[buf][kk][tx];            \
        *(float4*)&bv[4] = *(const float4*)&Bs[buf][kk][tx+4];          \
        _Pragma("unroll")                                               \
        for (int i = 0; i < 8; i++)                                     \
            _Pragma("unroll")                                           \
            for (int j = 0; j < 8; j++)                                 \
                acc[i][j] = fmaf(av[i], bv[j], acc[i][j]);              \
    }

// ------------------- SGEMM NT (3-stage pipeline, conflict-free stores):
// C = alpha*A[M,K]@B[N,K]^T (+bias)(/denom)(relu), with optional length-skip.
__global__ __launch_bounds__(256,2) void sgemm_nt(
    const float* __restrict__ A, int lda, long long sAo, long long sAi,
    const float* __restrict__ B, int ldb, long long sBo, long long sBi,
    float* __restrict__ C, int ldc, long long sCo, long long sCi,
    int innerZ, int K, float alpha,
    const float* __restrict__ bias, const float* __restrict__ denom, int relu,
    const int* __restrict__ lens, int colskip)
{
    int z = blockIdx.z; int zo = z / innerZ; int zi = z - zo*innerZ;
    if (lens) {
        int rowg = blockIdx.y*128;
        int bsm = (innerZ > 1) ? zo : (rowg >> 9);
        int lb = lens[bsm];
        int rloc = (innerZ > 1) ? rowg : (rowg & 511);
        if (rloc >= lb) return;
        if (colskip && blockIdx.x*128 >= lb) return;
    }
    A += zo*sAo + zi*sAi; B += zo*sBo + zi*sBi; C += zo*sCo + zi*sCi;
    __shared__ float As[3][8][128];
    __shared__ float Bs[3][8][128];
    int tid = threadIdx.x;
    int r = tid & 127;
    const float* G = (tid < 128)
        ? (A + (long long)(blockIdx.y*128 + r)*lda)
        : (B + (long long)(blockIdx.x*128 + r)*ldb);
    float (*S)[8][128] = (tid < 128) ? As : Bs;

    float acc[8][8];
#pragma unroll
    for (int i = 0; i < 8; i++)
#pragma unroll
        for (int j = 0; j < 8; j++) acc[i][j] = 0.f;
    int tx = (tid & 15) * 8;
    int ty = (tid >> 4) * 8;

    int KT = K >> 3;
    {
        float4 p0 = *(const float4*)(G + 0);
        float4 p1 = *(const float4*)(G + 4);
        S[0][0][r]=p0.x; S[0][1][r]=p0.y; S[0][2][r]=p0.z; S[0][3][r]=p0.w;
        S[0][4][r]=p1.x; S[0][5][r]=p1.y; S[0][6][r]=p1.z; S[0][7][r]=p1.w;
        p0 = *(const float4*)(G + 8);
        p1 = *(const float4*)(G + 12);
        S[1][0][r]=p0.x; S[1][1][r]=p0.y; S[1][2][r]=p0.z; S[1][3][r]=p0.w;
        S[1][4][r]=p1.x; S[1][5][r]=p1.y; S[1][6][r]=p1.z; S[1][7][r]=p1.w;
    }
    __syncthreads();
    int cur = 0;
    for (int kt = 2; kt < KT; kt++) {
        int k0 = kt << 3;
        float4 p0 = *(const float4*)(G + k0);
        float4 p1 = *(const float4*)(G + k0 + 4);
        COMPUTE_TILE(cur);
        int st = kt % 3;
        S[st][0][r]=p0.x; S[st][1][r]=p0.y; S[st][2][r]=p0.z; S[st][3][r]=p0.w;
        S[st][4][r]=p1.x; S[st][5][r]=p1.y; S[st][6][r]=p1.z; S[st][7][r]=p1.w;
        __syncthreads();
        cur++; if (cur == 3) cur = 0;
    }
    COMPUTE_TILE(cur);
    cur++; if (cur == 3) cur = 0;
    COMPUTE_TILE(cur);

    int rowBase = blockIdx.y*128 + ty;
    int colBase = blockIdx.x*128 + tx;
#pragma unroll
    for (int i = 0; i < 8; i++) {
        int row = rowBase + i;
        float rd = denom ? (1.0f/denom[row]) : 1.0f;
        float* crow = C + (long long)row*ldc + colBase;
#pragma unroll
        for (int j = 0; j < 8; j++) {
            float v = acc[i][j] * alpha;
            if (bias) v += bias[colBase + j];
            v *= rd;
            if (relu) v = fmaxf(v, 0.f);
            crow[j] = v;
        }
    }
}

// ------------------- SGEMM NN (batched, 3-stage): C = A[M,K]@B[K,N]
__global__ __launch_bounds__(256,2) void sgemm_nn(
    const float* __restrict__ A, int lda, long long sA,
    const float* __restrict__ B, int ldb, long long sB,
    float* __restrict__ C, int ldc, long long sC, int K,
    const int* __restrict__ lens)
{
    int z = blockIdx.z;
    if (lens) {
        int lb = lens[z];
        if (blockIdx.y*128 >= lb) return;
        int Keff = ((lb + 7) >> 3) << 3;
        if (Keff < K) K = Keff;
    }
    A += (long long)z*sA; B += (long long)z*sB; C += (long long)z*sC;
    __shared__ float As[3][8][128];
    __shared__ float Bs[3][8][128];
    int tid = threadIdx.x;
    int r = tid & 127;

    const float* G;
    int kRow = 0, cB = 0;
    if (tid < 128) {
        G = A + (long long)(blockIdx.y*128 + r)*lda;
    } else {
        kRow = r >> 4; cB = (r & 15) * 8;
        G = B + (long long)kRow*ldb + blockIdx.x*128 + cB;
    }

    float acc[8][8];
#pragma unroll
    for (int i = 0; i < 8; i++)
#pragma unroll
        for (int j = 0; j < 8; j++) acc[i][j] = 0.f;
    int tx = (tid & 15) * 8;
    int ty = (tid >> 4) * 8;

    int KT = K >> 3;
    if (tid < 128) {
        float4 p0 = *(const float4*)(G + 0);
        float4 p1 = *(const float4*)(G + 4);
        As[0][0][r]=p0.x; As[0][1][r]=p0.y; As[0][2][r]=p0.z; As[0][3][r]=p0.w;
        As[0][4][r]=p1.x; As[0][5][r]=p1.y; As[0][6][r]=p1.z; As[0][7][r]=p1.w;
        p0 = *(const float4*)(G + 8);
        p1 = *(const float4*)(G + 12);
        As[1][0][r]=p0.x; As[1][1][r]=p0.y; As[1][2][r]=p0.z; As[1][3][r]=p0.w;
        As[1][4][r]=p1.x; As[1][5][r]=p1.y; As[1][6][r]=p1.z; As[1][7][r]=p1.w;
    } else {
        float4 p0 = *(const float4*)(G);
        float4 p1 = *(const float4*)(G + 4);
        *(float4*)&Bs[0][kRow][cB]   = p0;
        *(float4*)&Bs[0][kRow][cB+4] = p1;
        p0 = *(const float4*)(G + (long long)8*ldb);
        p1 = *(const float4*)(G + (long long)8*ldb + 4);
        *(float4*)&Bs[1][kRow][cB]   = p0;
        *(float4*)&Bs[1][kRow][cB+4] = p1;
    }
    __syncthreads();
    int cur = 0;
    for (int kt = 2; kt < KT; kt++) {
        int k0 = kt << 3;
        float4 p0, p1;
        if (tid < 128) {
            p0 = *(const float4*)(G + k0);
            p1 = *(const float4*)(G + k0 + 4);
        } else {
            p0 = *(const float4*)(G + (long long)k0*ldb);
            p1 = *(const float4*)(G + (long long)k0*ldb + 4);
        }
        COMPUTE_TILE(cur);
        int st = kt % 3;
        if (tid < 128) {
            As[st][0][r]=p0.x; As[st][1][r]=p0.y; As[st][2][r]=p0.z; As[st][3][r]=p0.w;
            As[st][4][r]=p1.x; As[st][5][r]=p1.y; As[st][6][r]=p1.z; As[st][7][r]=p1.w;
        } else {
            *(float4*)&Bs[st][kRow][cB]   = p0;
            *(float4*)&Bs[st][kRow][cB+4] = p1;
        }
        __syncthreads();
        cur++; if (cur == 3) cur = 0;
    }
    COMPUTE_TILE(cur);
    cur++; if (cur == 3) cur = 0;
    COMPUTE_TILE(cur);

    int rowBase = blockIdx.y*128 + ty;
    int colBase = blockIdx.x*128 + tx;
#pragma unroll
    for (int i = 0; i < 8; i++) {
        float* crow = C + (long long)(rowBase+i)*ldc + colBase;
#pragma unroll
        for (int j = 0; j < 8; j++) crow[j] = acc[i][j];
    }
}

// ------------------- BiLSTM recurrence -------------------
// 128 blocks = 16 groups(8 length-sorted samples x dir) x 8 j-split, 256 thr.
// Barrier: bar.sync -> tid0 fence.gpu + relaxed red -> ld.acquire poll.
__global__ __launch_bounds__(256) void lstm_kernel(
    const float* __restrict__ Whhf, const float* __restrict__ Whhb,
    const int* __restrict__ l, float* __restrict__ gout)
{
    extern __shared__ float sm[];
    float* Ws = sm;                 // 32768 floats, f4 layout [k4][128 rows]
    float* hs = sm + 32768;         // [8][256]
    float* gs = hs + 2048;          // [8][128]
    float* cs = gs + 1024;          // [8][32]
    int bid = blockIdx.x; int group = bid >> 3; int q = bid & 7;
    int dir = group >> 3; int sg = group & 7;
    int tid = threadIdx.x;
    const float* Whh = dir ? Whhb : Whhf;
    const float* Xd = dir ? d_Xb : d_Xf;
    unsigned* barp = &d_barc[group];
    for (int idx = tid; idx < 32768; idx += 256) {
        int rr = idx >> 8; int kk = idx & 255;
        int gr = ((rr>>5)<<8) + (q<<5) + (rr&31);
        Ws[(((kk>>2)*128)+rr)*4 + (kk&3)] = Whh[gr*256 + kk];
    }
    cs[tid] = 0.f;
    // h starts at zero in smem (no t=0 global exchange)
    for (int idx = tid; idx < 2048; idx += 256) hs[idx] = 0.f;
    int ln[8]; int smp[8]; int lmax = 0;
#pragma unroll
    for (int n = 0; n < 8; n++) {
        int s = d_perm[sg*8+n];
        smp[n] = s; ln[n] = l[s];
        lmax = max(lmax, ln[n]);
    }
    int slot = tid >> 7; int r = tid & 127;
    int n0 = slot*4;                 // samples n0..n0+3
    int grow = ((r>>5)<<8) + (q<<5) + (r&31);
    __syncthreads();
    const float4* Ws4 = (const float4*)Ws;

    // prefetch X(t=0)
    float xr0=0.f, xr1=0.f, xr2=0.f, xr3=0.f;
    {
        if (0 < ln[n0+0]) { int tt = dir ? (ln[n0+0]-1) : 0; xr0 = Xd[((long long)(smp[n0+0]*SS+tt)<<10) + grow]; }
        if (0 < ln[n0+1]) { int tt = dir ? (ln[n0+1]-1) : 0; xr1 = Xd[((long long)(smp[n0+1]*SS+tt)<<10) + grow]; }
        if (0 < ln[n0+2]) { int tt = dir ? (ln[n0+2]-1) : 0; xr2 = Xd[((long long)(smp[n0+2]*SS+tt)<<10) + grow]; }
        if (0 < ln[n0+3]) { int tt = dir ? (ln[n0+3]-1) : 0; xr3 = Xd[((long long)(smp[n0+3]*SS+tt)<<10) + grow]; }
    }

    for (int t = 0; t < lmax; t++) {
        float acc0 = xr0, acc1 = xr1, acc2 = xr2, acc3 = xr3;
        const float4* h0 = (const float4*)(hs + (n0+0)*256);
        const float4* h1 = (const float4*)(hs + (n0+1)*256);
        const float4* h2 = (const float4*)(hs + (n0+2)*256);
        const float4* h3 = (const float4*)(hs + (n0+3)*256);
#pragma unroll 8
        for (int k4 = 0; k4 < 64; k4++) {
            float4 w = Ws4[k4*128 + r];
            float4 a = h0[k4], b = h1[k4], c = h2[k4], d = h3[k4];
            acc0 = fmaf(w.x,a.x, fmaf(w.y,a.y, fmaf(w.z,a.z, fmaf(w.w,a.w, acc0))));
            acc1 = fmaf(w.x,b.x, fmaf(w.y,b.y, fmaf(w.z,b.z, fmaf(w.w,b.w, acc1))));
            acc2 = fmaf(w.x,c.x, fmaf(w.y,c.y, fmaf(w.z,c.z, fmaf(w.w,c.w, acc2))));
            acc3 = fmaf(w.x,d.x, fmaf(w.y,d.y, fmaf(w.z,d.z, fmaf(w.w,d.w, acc3))));
        }
        gs[(n0+0)*128 + r] = acc0;
        gs[(n0+1)*128 + r] = acc1;
        gs[(n0+2)*128 + r] = acc2;
        gs[(n0+3)*128 + r] = acc3;
        __syncthreads();
        {
            int n = tid >> 5, jl = tid & 31;
            if (t < ln[n]) {
                float gi = gs[n*128+jl], gf = gs[n*128+32+jl];
                float gg = gs[n*128+64+jl], go_ = gs[n*128+96+jl];
                float c = cs[n*32+jl];
                c = (1.f/(1.f+expf(-gf)))*c + (1.f/(1.f+expf(-gi)))*tanhf(gg);
                float h = (1.f/(1.f+expf(-go_)))*tanhf(c);
                cs[n*32+jl] = c;
                float* dst = (float*)&d_hx4[((t+1)&1)*8192 + group*512];
                __stcg(dst + n*256 + q*32 + jl, h);
                int bsm = smp[n];
                int tpos = dir ? (ln[n]-1-t) : t;
                gout[((long long)(bsm*SS+tpos))*512 + dir*256 + q*32 + jl] = h;
            }
        }
        if (t+1 == lmax) break;
        __syncthreads();   // all h stores issued before tid0's fence
        if (tid == 0) {
            __threadfence();                 // cumulative: publishes block's stores
            atomicAdd(barp, 1u);             // relaxed arrive
        }
        // prefetch X(t+1) while waiting
        int tn = t+1;
        xr0 = xr1 = xr2 = xr3 = 0.f;
        if (tn < ln[n0+0]) { int tt = dir ? (ln[n0+0]-1-tn) : tn; xr0 = Xd[((long long)(smp[n0+0]*SS+tt)<<10) + grow]; }
        if (tn < ln[n0+1]) { int tt = dir ? (ln[n0+1]-1-tn) : tn; xr1 = Xd[((long long)(smp[n0+1]*SS+tt)<<10) + grow]; }
        if (tn < ln[n0+2]) { int tt = dir ? (ln[n0+2]-1-tn) : tn; xr2 = Xd[((long long)(smp[n0+2]*SS+tt)<<10) + grow]; }
        if (tn < ln[n0+3]) { int tt = dir ? (ln[n0+3]-1-tn) : tn; xr3 = Xd[((long long)(smp[n0+3]*SS+tt)<<10) + grow]; }
        if (tid == 0) {
            unsigned tgt = (unsigned)(t+1)*8u;
            unsigned v;
            do {
                asm volatile("ld.acquire.gpu.global.u32 %0, [%1];" : "=r"(v) : "l"(barp));
            } while (v < tgt);
        }
        __syncthreads();
        // pull peers' h slices for step t+1
        ((float4*)hs)[tid]     = __ldcg(&d_hx4[((t+1)&1)*8192 + group*512 + tid]);
        ((float4*)hs)[tid+256] = __ldcg(&d_hx4[((t+1)&1)*8192 + group*512 + tid + 256]);
        __syncthreads();
    }
}

// ------------------- masked softmax + head mean + diag -------------------
__global__ void softmax_kernel(const int* __restrict__ l, float* __restrict__ ag) {
    int row = blockIdx.x; int b = row >> 9; int i = row & 511;
    int lb = l[b];
    float* out = ag + (long long)row*512;
    int tid = threadIdx.x;
    if (i >= lb) { out[tid] = 0.f; out[tid+256] = 0.f; return; }
    __shared__ float red[8];
    float a0 = 0.f, a1 = 0.f;
    int lane = tid & 31, wid = tid >> 5;
    for (int h = 0; h < 4; h++) {
        const float* sr = d_scores + ((long long)((b*4+h)*512 + i))*512;
        float v0 = (tid < lb)     ? sr[tid]     : -3.0e38f;
        float v1 = (tid+256 < lb) ? sr[tid+256] : -3.0e38f;
        float m = fmaxf(v0, v1);
        for (int o = 16; o; o >>= 1) m = fmaxf(m, __shfl_xor_sync(0xffffffffu, m, o));
        if (lane == 0) red[wid] = m;
        __syncthreads();
        m = red[0];
#pragma unroll
        for (int w = 1; w < 8; w++) m = fmaxf(m, red[w]);
        __syncthreads();
        float e0 = (tid < lb)     ? expf(v0 - m) : 0.f;
        float e1 = (tid+256 < lb) ? expf(v1 - m) : 0.f;
        float s = e0 + e1;
        for (int o = 16; o; o >>= 1) s += __shfl_xor_sync(0xffffffffu, s, o);
        if (lane == 0) red[wid] = s;
        __syncthreads();
        s = 0.f;
#pragma unroll
        for (int w = 0; w < 8; w++) s += red[w];
        float inv = 1.f/s;
        a0 += e0*inv; a1 += e1*inv;
        __syncthreads();
    }
    a0 *= 0.25f; a1 *= 0.25f;
    if (tid == i) a0 = 1.f;
    if (tid+256 == i) a1 = 1.f;
    out[tid] = a0; out[tid+256] = a1;
}

// ------------- exact kk-th smallest nonzero via 4-pass radix select ----------
__global__ __launch_bounds__(1024) void kth_kernel(const float* __restrict__ ag) {
    __shared__ unsigned wh[32][256];
    __shared__ unsigned chist[256];
    __shared__ int s_k, s_rem; __shared__ unsigned s_pref;
    int b = blockIdx.x; int tid = threadIdx.x; int wid = tid >> 5;
    const float* f = ag + (long long)b*262144;
    for (int pass = 0; pass < 4; pass++) {
        int shift = 24 - 8*pass;
        for (int j = tid; j < 32*256; j += 1024) ((unsigned*)wh)[j] = 0u;
        __syncthreads();
        unsigned pref = (pass == 0) ? 0u : s_pref;
        unsigned prefHi = pref >> (shift+8);
        for (int j = tid; j < 262144; j += 1024) {
            unsigned ub = __float_as_uint(f[j]);
            if (ub != 0u) {
                if (pass == 0 || (ub >> (shift+8)) == prefHi)
                    atomicAdd(&wh[wid][(ub >> shift) & 255u], 1u);
            }
        }
        __syncthreads();
        if (tid < 256) {
            unsigned s = 0;
#pragma unroll
            for (int w = 0; w < 32; w++) s += wh[w][tid];
            chist[tid] = s;
        }
        __syncthreads();
        if (tid == 0) {
            if (pass == 0) {
                unsigned nnz = 0;
                for (int c = 0; c < 256; c++) nnz += chist[c];
                int kk = (int)floorf((float)((int)nnz - 512) * 0.3f);
                s_k = kk; s_rem = kk; s_pref = 0u;
            }
            if (s_k > 0) {
                int rem = s_rem; unsigned pf = s_pref;
                for (int c = 0; c < 256; c++) {
                    if ((int)chist[c] >= rem) { pf |= ((unsigned)c) << shift; break; }
                    rem -= (int)chist[c];
                }
                s_rem = rem; s_pref = pf;
            }
        }
        __syncthreads();
        if (s_k <= 0) break;
    }
    if (tid == 0) d_thre[b] = (s_k > 0) ? __uint_as_float(s_pref) : 0.f;
}

// ------------------- prune + ensemble + denom -------------------
__global__ void prune_kernel(const float* __restrict__ adj, float* __restrict__ ag) {
    int row = blockIdx.x; int b = row >> 9; int tid = threadIdx.x;
    float thre = d_thre[b];
    long long base = (long long)row*512;
    float s = 0.f;
#pragma unroll
    for (int u = 0; u < 2; u++) {
        int j = tid + u*256;
        float v = ag[base + j];
        v = (v <= thre) ? 0.f : v;
        ag[base + j] = v;
        float e = 0.5f*adj[base + j] + 0.5f*v;
        d_adjens[base + j] = e;
        s += e;
    }
    for (int o = 16; o; o >>= 1) s += __shfl_xor_sync(0xffffffffu, s, o);
    __shared__ float red[8];
    if ((tid & 31) == 0) red[tid >> 5] = s;
    __syncthreads();
    if (tid == 0) {
        float tot = 0.f;
#pragma unroll
        for (int w = 0; w < 8; w++) tot += red[w];
        d_denom[row] = tot + 1.f;
    }
}

// ------------------- host launcher -------------------
extern "C" void kernel_launch(void* const* d_in, const int* in_sizes, int n_in,
                              void* d_out, int out_size) {
    const float* adj    = (const float*)d_in[0];
    const int*   tok    = (const int*)d_in[1];
    const int*   pos    = (const int*)d_in[2];
    const int*   post   = (const int*)d_in[3];
    const int*   l      = (const int*)d_in[4];
    const float* emb    = (const float*)d_in[5];
    const float* pose   = (const float*)d_in[6];
    const float* poste  = (const float*)d_in[7];
    const float* Wih_f  = (const float*)d_in[8];
    const float* Whh_f  = (const float*)d_in[9];
    const float* bih_f  = (const float*)d_in[10];
    const float* bhh_f  = (const float*)d_in[11];
    const float* Wih_b  = (const float*)d_in[12];
    const float* Whh_b  = (const float*)d_in[13];
    const float* bih_b  = (const float*)d_in[14];
    const float* bhh_b  = (const float*)d_in[15];
    const float* Wq     = (const float*)d_in[16];
    const float* bq     = (const float*)d_in[17];
    const float* Wk     = (const float*)d_in[18];
    const float* bk     = (const float*)d_in[19];
    const float* W0     = (const float*)d_in[20];
    const float* b0     = (const float*)d_in[21];
    const float* W1     = (const float*)d_in[22];
    const float* b1     = (const float*)d_in[23];

    float* xo = (float*)d_out;                      // [B,S,256]
    float* ag = xo + 8388608;                       // [B,S,S]
    float* go = xo + 25165824;                      // [B,S,512]

    void *pv;
    cudaGetSymbolAddress(&pv, d_embs);   float* embs   = (float*)pv;
    cudaGetSymbolAddress(&pv, d_Xf);     float* Xf     = (float*)pv;
    cudaGetSymbolAddress(&pv, d_Xb);     float* Xb     = (float*)pv;
    cudaGetSymbolAddress(&pv, d_q);      float* qb     = (float*)pv;
    cudaGetSymbolAddress(&pv, d_k);      float* kb     = (float*)pv;
    cudaGetSymbolAddress(&pv, d_scores); float* sc     = (float*)pv;
    cudaGetSymbolAddress(&pv, d_adjens); float* ens    = (float*)pv;
    cudaGetSymbolAddress(&pv, d_tb);     float* tbuf   = (float*)pv;
    cudaGetSymbolAddress(&pv, d_x1);     float* x1     = (float*)pv;
    cudaGetSymbolAddress(&pv, d_denom);  float* den    = (float*)pv;
    cudaGetSymbolAddress(&pv, d_biasf);  float* biasf  = (float*)pv;
    cudaGetSymbolAddress(&pv, d_biasb);  float* biasb  = (float*)pv;

    cudaMemsetAsync(go, 0, (size_t)NROWS*512*sizeof(float));
    prep_kernel<<<4,256>>>(bih_f, bhh_f, bih_b, bhh_b);
    init_kernel<<<16,1024>>>();
    sort_kernel<<<1,64>>>(l);
    embed_kernel<<<32768,128>>>(tok, pos, post, emb, pose, poste);

    // X = embs @ Wih^T + bias   [32768,1024]  (skip row tiles beyond l[b])
    sgemm_nt<<<dim3(8,256,1),256>>>(embs,360,0,0, Wih_f,360,0,0, Xf,1024,0,0,
                                    1,360,1.f, biasf, nullptr, 0, l, 0);
    sgemm_nt<<<dim3(8,256,1),256>>>(embs,360,0,0, Wih_b,360,0,0, Xb,1024,0,0,
                                    1,360,1.f, biasb, nullptr, 0, l, 0);

    cudaFuncSetAttribute(lstm_kernel, cudaFuncAttributeMaxDynamicSharedMemorySize, 36096*4);
    lstm_kernel<<<128,256,36096*4>>>(Whh_f, Whh_b, l, go);

    // q, k (skip row tiles beyond l[b])
    sgemm_nt<<<dim3(4,256,1),256>>>(go,512,0,0, Wq,512,0,0, qb,512,0,0,
                                    1,512,1.f, bq, nullptr, 0, l, 0);
    sgemm_nt<<<dim3(4,256,1),256>>>(go,512,0,0, Wk,512,0,0, kb,512,0,0,
                                    1,512,1.f, bk, nullptr, 0, l, 0);
    // scores[b,h] = q_bh @ k_bh^T / sqrt(128)  (skip row AND col tiles >= l[b])
    float alpha = 1.f/sqrtf(128.f);
    sgemm_nt<<<dim3(4,4,256),256>>>(qb,512, 262144,128, kb,512, 262144,128,
                                    sc,512, 1048576,262144, 4,128, alpha,
                                    nullptr, nullptr, 0, l, 1);
    softmax_kernel<<<32768,256>>>(l, ag);
    kth_kernel<<<64,1024>>>(ag);
    prune_kernel<<<32768,256>>>(adj, ag);

    // GCN layer 1: t = adjens @ g ; x1 = relu((t@W0^T+b0)/denom)
    cudaMemsetAsync(tbuf, 0, (size_t)16777216*sizeof(float));
    sgemm_nn<<<dim3(4,4,64),256>>>(ens,512,262144, go,512,262144, tbuf,512,262144, 512, l);
    sgemm_nt<<<dim3(2,256,1),256>>>(tbuf,512,0,0, W0,512,0,0, x1,256,0,0,
                                    1,512,1.f, b0, den, 1, nullptr, 0);
    // GCN layer 2: t2 = adjens @ x1 ; x = relu((t2@W1^T+b1)/denom)
    cudaMemsetAsync(tbuf, 0, (size_t)8388608*sizeof(float));
    sgemm_nn<<<dim3(2,4,64),256>>>(ens,512,262144, x1,256,131072, tbuf,256,131072, 512, l);
    sgemm_nt<<<dim3(2,256,1),256>>>(tbuf,256,0,0, W1,256,0,0, xo,256,0,0,
                                    1,256,1.f, b1, den, 1, nullptr, 0);
    (void)in_sizes; (void)n_in; (void)out_size;
}

// round 10
// speedup vs baseline: 1.1279x; 1.0320x over previous
#include <cuda_runtime.h>
#include <math.h>

#define SS 512
#define NROWS 32768LL

// ------------------- device scratch (no allocs allowed) -------------------
__device__ float d_embs[32768*360];
__device__ float d_Xf[32768*1024];
__device__ float d_Xb[32768*1024];
__device__ float d_q[32768*512];
__device__ float d_k[32768*512];
__device__ float d_scores[67108864];
__device__ float d_adjens[16777216];
__device__ float d_tb[16777216];
__device__ float d_x1[8388608];
__device__ float d_denom[32768];
__device__ float d_thre[64];
__device__ float d_biasf[1024];
__device__ float d_biasb[1024];
__device__ float4 d_hx4[2*16*512];
__device__ unsigned d_barc[16];
__device__ int d_perm[64];

// ------------------- small prep kernels -------------------
__global__ void prep_kernel(const float* bihf, const float* bhhf,
                            const float* bihb, const float* bhhb) {
    int i = blockIdx.x*blockDim.x + threadIdx.x;
    if (i < 1024) { d_biasf[i] = bihf[i]+bhhf[i]; d_biasb[i] = bihb[i]+bhhb[i]; }
}

__global__ void init_kernel() {
    int i = blockIdx.x*blockDim.x + threadIdx.x;
    if (i < 16) d_barc[i] = 0u;
    float4 z = make_float4(0.f,0.f,0.f,0.f);
    for (int j = i; j < 2*16*512; j += blockDim.x*gridDim.x) d_hx4[j] = z;
}

// rank-sort 64 lengths ascending -> d_perm (stable)
__global__ void sort_kernel(const int* __restrict__ l) {
    int i = threadIdx.x;
    int li = l[i]; int r = 0;
    for (int j = 0; j < 64; j++) {
        int lj = l[j];
        r += (lj < li) || (lj == li && j < i);
    }
    d_perm[r] = i;
}

__global__ void embed_kernel(const int* __restrict__ tok, const int* __restrict__ pos,
                             const int* __restrict__ post, const float* __restrict__ emb,
                             const float* __restrict__ pose, const float* __restrict__ poste) {
    int r = blockIdx.x;
    int t = tok[r], p = pos[r], q = post[r];
    float* o = d_embs + (long long)r*360;
    for (int d = threadIdx.x; d < 360; d += blockDim.x) {
        float v;
        if (d < 300)      v = emb[(long long)t*300 + d];
        else if (d < 330) v = pose[p*30 + (d-300)];
        else              v = poste[q*30 + (d-330)];
        o[d] = v;
    }
}

// ------------------- tf32 helpers -------------------
__device__ __forceinline__ unsigned f2tf(float x) {
    unsigned r; asm("cvt.rna.tf32.f32 %0, %1;" : "=r"(r) : "f"(x)); return r;
}
__device__ __forceinline__ void split8(float4 p0, float4 p1,
                                       unsigned* bg, unsigned* sv) {
    float v[8] = {p0.x,p0.y,p0.z,p0.w,p1.x,p1.y,p1.z,p1.w};
#pragma unroll
    for (int i = 0; i < 8; i++) {
        unsigned b = f2tf(v[i]);
        bg[i] = b;
        sv[i] = f2tf(v[i] - __uint_as_float(b));
    }
}

#define MMA_TF32(c, a, b)                                                   \
    asm volatile("mma.sync.aligned.m16n8k8.row.col.f32.tf32.tf32.f32 "      \
        "{%0,%1,%2,%3},{%4,%5,%6,%7},{%8,%9},{%0,%1,%2,%3};"                \
        : "+f"((c)[0]), "+f"((c)[1]), "+f"((c)[2]), "+f"((c)[3])            \
        : "r"((a)[0]), "r"((a)[1]), "r"((a)[2]), "r"((a)[3]),               \
          "r"((b)[0]), "r"((b)[1]))

#define FRAG_LOADS(cur)                                                     \
    unsigned ab[4][4], asx[4][4], bbf[4][2], bsf[4][2];                     \
    _Pragma("unroll")                                                       \
    for (int mt = 0; mt < 4; mt++) {                                        \
        int rr = wr + mt*16 + g;                                            \
        ab[mt][0]  = sAb[cur][rr][t4];   ab[mt][1]  = sAb[cur][rr+8][t4];   \
        ab[mt][2]  = sAb[cur][rr][t4+4]; ab[mt][3]  = sAb[cur][rr+8][t4+4]; \
        asx[mt][0] = sAs[cur][rr][t4];   asx[mt][1] = sAs[cur][rr+8][t4];   \
        asx[mt][2] = sAs[cur][rr][t4+4]; asx[mt][3] = sAs[cur][rr+8][t4+4]; \
    }                                                                       \
    _Pragma("unroll")                                                       \
    for (int nt = 0; nt < 4; nt++) {                                        \
        int cc = wc + nt*8 + g;                                             \
        bbf[nt][0] = sBb[cur][t4][cc];   bbf[nt][1] = sBb[cur][t4+4][cc];   \
        bsf[nt][0] = sBs[cur][t4][cc];   bsf[nt][1] = sBs[cur][t4+4][cc];   \
    }                                                                       \
    _Pragma("unroll")                                                       \
    for (int mt = 0; mt < 4; mt++)                                          \
        _Pragma("unroll")                                                   \
        for (int nt = 0; nt < 4; nt++) {                                    \
            MMA_TF32(c[mt][nt], ab[mt], bbf[nt]);                           \
            MMA_TF32(c[mt][nt], ab[mt], bsf[nt]);                           \
            MMA_TF32(c[mt][nt], asx[mt], bbf[nt]);                          \
        }

// ------------------- tf32 MMA GEMM NT (3xTF32, fp32-accurate):
// C = alpha*A[M,K]@B[N,K]^T (+bias)(/denom)(relu), with optional length-skip.
__global__ __launch_bounds__(256,1) void mma_nt(
    const float* __restrict__ A, int lda, long long sAo, long long sAi,
    const float* __restrict__ B, int ldb, long long sBo, long long sBi,
    float* __restrict__ C, int ldc, long long sCo, long long sCi,
    int innerZ, int K, float alpha,
    const float* __restrict__ bias, const float* __restrict__ denom, int relu,
    const int* __restrict__ lens, int colskip)
{
    int z = blockIdx.z; int zo = z / innerZ; int zi = z - zo*innerZ;
    if (lens) {
        int rowg = blockIdx.y*128;
        int bsm = (innerZ > 1) ? zo : (rowg >> 9);
        int lb = lens[bsm];
        int rloc = (innerZ > 1) ? rowg : (rowg & 511);
        if (rloc >= lb) return;
        if (colskip && blockIdx.x*128 >= lb) return;
    }
    A += zo*sAo + zi*sAi; B += zo*sBo + zi*sBi; C += zo*sCo + zi*sCi;
    __shared__ unsigned sAb[2][128][12], sAs[2][128][12];
    __shared__ unsigned sBb[2][8][132],  sBs[2][8][132];
    int tid = threadIdx.x; int r = tid & 127;
    bool isA = tid < 128;
    const float* G = isA ? (A + (long long)(blockIdx.y*128 + r)*lda)
                         : (B + (long long)(blockIdx.x*128 + r)*ldb);
    {
        float4 p0 = *(const float4*)G;
        float4 p1 = *(const float4*)(G + 4);
        unsigned bg[8], sv[8]; split8(p0, p1, bg, sv);
        if (isA) {
#pragma unroll
            for (int i = 0; i < 8; i++) { sAb[0][r][i] = bg[i]; sAs[0][r][i] = sv[i]; }
        } else {
#pragma unroll
            for (int i = 0; i < 8; i++) { sBb[0][i][r] = bg[i]; sBs[0][i][r] = sv[i]; }
        }
    }
    __syncthreads();
    int warp = tid >> 5, lane = tid & 31, g = lane >> 2, t4 = lane & 3;
    int wr = (warp >> 2) * 64, wc = (warp & 3) * 32;
    float c[4][4][4];
#pragma unroll
    for (int i = 0; i < 4; i++)
#pragma unroll
        for (int j = 0; j < 4; j++)
#pragma unroll
            for (int k = 0; k < 4; k++) c[i][j][k] = 0.f;
    int KT = K >> 3;
    for (int kt = 0; kt < KT; kt++) {
        int cur = kt & 1;
        float4 p0, p1;
        bool more = (kt + 1 < KT);
        if (more) {
            p0 = *(const float4*)(G + (kt+1)*8);
            p1 = *(const float4*)(G + (kt+1)*8 + 4);
        }
        FRAG_LOADS(cur);
        if (more) {
            unsigned bg[8], sv[8]; split8(p0, p1, bg, sv);
            int nx = (kt + 1) & 1;
            if (isA) {
#pragma unroll
                for (int i = 0; i < 8; i++) { sAb[nx][r][i] = bg[i]; sAs[nx][r][i] = sv[i]; }
            } else {
#pragma unroll
                for (int i = 0; i < 8; i++) { sBb[nx][i][r] = bg[i]; sBs[nx][i][r] = sv[i]; }
            }
            __syncthreads();
        }
    }
#pragma unroll
    for (int mt = 0; mt < 4; mt++)
#pragma unroll
        for (int nt = 0; nt < 4; nt++) {
            int row0 = blockIdx.y*128 + wr + mt*16 + g;
            int col0 = blockIdx.x*128 + wc + nt*8 + t4*2;
            float rd0 = denom ? (1.0f/denom[row0])   : 1.0f;
            float rd1 = denom ? (1.0f/denom[row0+8]) : 1.0f;
            float b0v = bias ? bias[col0]   : 0.f;
            float b1v = bias ? bias[col0+1] : 0.f;
            float v00 = (c[mt][nt][0]*alpha + b0v) * rd0;
            float v01 = (c[mt][nt][1]*alpha + b1v) * rd0;
            float v10 = (c[mt][nt][2]*alpha + b0v) * rd1;
            float v11 = (c[mt][nt][3]*alpha + b1v) * rd1;
            if (relu) {
                v00 = fmaxf(v00, 0.f); v01 = fmaxf(v01, 0.f);
                v10 = fmaxf(v10, 0.f); v11 = fmaxf(v11, 0.f);
            }
            *(float2*)&C[(long long)row0*ldc + col0]     = make_float2(v00, v01);
            *(float2*)&C[(long long)(row0+8)*ldc + col0] = make_float2(v10, v11);
        }
}

// ------------------- tf32 MMA GEMM NN (batched, 3xTF32): C = A[M,K]@B[K,N]
// lens: per-z sample length; skip row tiles >= l (C pre-zeroed) and clamp K.
__global__ __launch_bounds__(256,1) void mma_nn(
    const float* __restrict__ A, int lda, long long sA,
    const float* __restrict__ B, int ldb, long long sB,
    float* __restrict__ C, int ldc, long long sC, int K,
    const int* __restrict__ lens)
{
    int z = blockIdx.z;
    if (lens) {
        int lb = lens[z];
        if (blockIdx.y*128 >= lb) return;
        int Keff = ((lb + 7) >> 3) << 3;
        if (Keff < K) K = Keff;
    }
    A += (long long)z*sA; B += (long long)z*sB; C += (long long)z*sC;
    __shared__ unsigned sAb[2][128][12], sAs[2][128][12];
    __shared__ unsigned sBb[2][8][132],  sBs[2][8][132];
    int tid = threadIdx.x; int r = tid & 127;
    bool isA = tid < 128;
    const float* G;
    int kRow = 0, cB = 0;
    if (isA) {
        G = A + (long long)(blockIdx.y*128 + r)*lda;
    } else {
        kRow = r >> 4; cB = (r & 15) * 8;
        G = B + (long long)kRow*ldb + blockIdx.x*128 + cB;
    }
    {
        float4 p0 = *(const float4*)G;
        float4 p1 = *(const float4*)(G + 4);
        unsigned bg[8], sv[8]; split8(p0, p1, bg, sv);
        if (isA) {
#pragma unroll
            for (int i = 0; i < 8; i++) { sAb[0][r][i] = bg[i]; sAs[0][r][i] = sv[i]; }
        } else {
#pragma unroll
            for (int i = 0; i < 8; i++) { sBb[0][kRow][cB+i] = bg[i]; sBs[0][kRow][cB+i] = sv[i]; }
        }
    }
    __syncthreads();
    int warp = tid >> 5, lane = tid & 31, g = lane >> 2, t4 = lane & 3;
    int wr = (warp >> 2) * 64, wc = (warp & 3) * 32;
    float c[4][4][4];
#pragma unroll
    for (int i = 0; i < 4; i++)
#pragma unroll
        for (int j = 0; j < 4; j++)
#pragma unroll
            for (int k = 0; k < 4; k++) c[i][j][k] = 0.f;
    int KT = K >> 3;
    for (int kt = 0; kt < KT; kt++) {
        int cur = kt & 1;
        float4 p0, p1;
        bool more = (kt + 1 < KT);
        if (more) {
            if (isA) {
                p0 = *(const float4*)(G + (kt+1)*8);
                p1 = *(const float4*)(G + (kt+1)*8 + 4);
            } else {
                p0 = *(const float4*)(G + (long long)(kt+1)*8*ldb);
                p1 = *(const float4*)(G + (long long)(kt+1)*8*ldb + 4);
            }
        }
        FRAG_LOADS(cur);
        if (more) {
            unsigned bg[8], sv[8]; split8(p0, p1, bg, sv);
            int nx = (kt + 1) & 1;
            if (isA) {
#pragma unroll
                for (int i = 0; i < 8; i++) { sAb[nx][r][i] = bg[i]; sAs[nx][r][i] = sv[i]; }
            } else {
#pragma unroll
                for (int i = 0; i < 8; i++) { sBb[nx][kRow][cB+i] = bg[i]; sBs[nx][kRow][cB+i] = sv[i]; }
            }
            __syncthreads();
        }
    }
#pragma unroll
    for (int mt = 0; mt < 4; mt++)
#pragma unroll
        for (int nt = 0; nt < 4; nt++) {
            int row0 = blockIdx.y*128 + wr + mt*16 + g;
            int col0 = blockIdx.x*128 + wc + nt*8 + t4*2;
            *(float2*)&C[(long long)row0*ldc + col0]     = make_float2(c[mt][nt][0], c[mt][nt][1]);
            *(float2*)&C[(long long)(row0+8)*ldc + col0] = make_float2(c[mt][nt][2], c[mt][nt][3]);
        }
}

// ------------------- BiLSTM recurrence (R6, passing) -------------------
__global__ __launch_bounds__(256) void lstm_kernel(
    const float* __restrict__ Whhf, const float* __restrict__ Whhb,
    const int* __restrict__ l, float* __restrict__ gout)
{
    extern __shared__ float sm[];
    float* Ws = sm;
    float* hs = sm + 32768;
    float* gs = hs + 2048;
    float* cs = gs + 1024;
    int bid = blockIdx.x; int group = bid >> 3; int q = bid & 7;
    int dir = group >> 3; int sg = group & 7;
    int tid = threadIdx.x;
    const float* Whh = dir ? Whhb : Whhf;
    const float* Xd = dir ? d_Xb : d_Xf;
    unsigned* barp = &d_barc[group];
    for (int idx = tid; idx < 32768; idx += 256) {
        int rr = idx >> 8; int kk = idx & 255;
        int gr = ((rr>>5)<<8) + (q<<5) + (rr&31);
        Ws[(((kk>>2)*128)+rr)*4 + (kk&3)] = Whh[gr*256 + kk];
    }
    cs[tid] = 0.f;
    for (int idx = tid; idx < 2048; idx += 256) hs[idx] = 0.f;
    int ln[8]; int smp[8]; int lmax = 0;
#pragma unroll
    for (int n = 0; n < 8; n++) {
        int s = d_perm[sg*8+n];
        smp[n] = s; ln[n] = l[s];
        lmax = max(lmax, ln[n]);
    }
    int slot = tid >> 7; int r = tid & 127;
    int n0 = slot*4;
    int grow = ((r>>5)<<8) + (q<<5) + (r&31);
    __syncthreads();
    const float4* Ws4 = (const float4*)Ws;

    float xr0=0.f, xr1=0.f, xr2=0.f, xr3=0.f;
    {
        if (0 < ln[n0+0]) { int tt = dir ? (ln[n0+0]-1) : 0; xr0 = Xd[((long long)(smp[n0+0]*SS+tt)<<10) + grow]; }
        if (0 < ln[n0+1]) { int tt = dir ? (ln[n0+1]-1) : 0; xr1 = Xd[((long long)(smp[n0+1]*SS+tt)<<10) + grow]; }
        if (0 < ln[n0+2]) { int tt = dir ? (ln[n0+2]-1) : 0; xr2 = Xd[((long long)(smp[n0+2]*SS+tt)<<10) + grow]; }
        if (0 < ln[n0+3]) { int tt = dir ? (ln[n0+3]-1) : 0; xr3 = Xd[((long long)(smp[n0+3]*SS+tt)<<10) + grow]; }
    }

    for (int t = 0; t < lmax; t++) {
        float acc0 = xr0, acc1 = xr1, acc2 = xr2, acc3 = xr3;
        const float4* h0 = (const float4*)(hs + (n0+0)*256);
        const float4* h1 = (const float4*)(hs + (n0+1)*256);
        const float4* h2 = (const float4*)(hs + (n0+2)*256);
        const float4* h3 = (const float4*)(hs + (n0+3)*256);
#pragma unroll 8
        for (int k4 = 0; k4 < 64; k4++) {
            float4 w = Ws4[k4*128 + r];
            float4 a = h0[k4], b = h1[k4], cc = h2[k4], d = h3[k4];
            acc0 = fmaf(w.x,a.x, fmaf(w.y,a.y, fmaf(w.z,a.z, fmaf(w.w,a.w, acc0))));
            acc1 = fmaf(w.x,b.x, fmaf(w.y,b.y, fmaf(w.z,b.z, fmaf(w.w,b.w, acc1))));
            acc2 = fmaf(w.x,cc.x, fmaf(w.y,cc.y, fmaf(w.z,cc.z, fmaf(w.w,cc.w, acc2))));
            acc3 = fmaf(w.x,d.x, fmaf(w.y,d.y, fmaf(w.z,d.z, fmaf(w.w,d.w, acc3))));
        }
        gs[(n0+0)*128 + r] = acc0;
        gs[(n0+1)*128 + r] = acc1;
        gs[(n0+2)*128 + r] = acc2;
        gs[(n0+3)*128 + r] = acc3;
        __syncthreads();
        {
            int n = tid >> 5, jl = tid & 31;
            if (t < ln[n]) {
                float gi = gs[n*128+jl], gf = gs[n*128+32+jl];
                float gg = gs[n*128+64+jl], go_ = gs[n*128+96+jl];
                float c = cs[n*32+jl];
                c = (1.f/(1.f+expf(-gf)))*c + (1.f/(1.f+expf(-gi)))*tanhf(gg);
                float h = (1.f/(1.f+expf(-go_)))*tanhf(c);
                cs[n*32+jl] = c;
                float* dst = (float*)&d_hx4[((t+1)&1)*8192 + group*512];
                __stcg(dst + n*256 + q*32 + jl, h);
                int bsm = smp[n];
                int tpos = dir ? (ln[n]-1-t) : t;
                gout[((long long)(bsm*SS+tpos))*512 + dir*256 + q*32 + jl] = h;
            }
        }
        if (t+1 == lmax) break;
        __syncthreads();
        if (tid == 0) {
            __threadfence();
            atomicAdd(barp, 1u);
        }
        int tn = t+1;
        xr0 = xr1 = xr2 = xr3 = 0.f;
        if (tn < ln[n0+0]) { int tt = dir ? (ln[n0+0]-1-tn) : tn; xr0 = Xd[((long long)(smp[n0+0]*SS+tt)<<10) + grow]; }
        if (tn < ln[n0+1]) { int tt = dir ? (ln[n0+1]-1-tn) : tn; xr1 = Xd[((long long)(smp[n0+1]*SS+tt)<<10) + grow]; }
        if (tn < ln[n0+2]) { int tt = dir ? (ln[n0+2]-1-tn) : tn; xr2 = Xd[((long long)(smp[n0+2]*SS+tt)<<10) + grow]; }
        if (tn < ln[n0+3]) { int tt = dir ? (ln[n0+3]-1-tn) : tn; xr3 = Xd[((long long)(smp[n0+3]*SS+tt)<<10) + grow]; }
        if (tid == 0) {
            unsigned tgt = (unsigned)(t+1)*8u;
            unsigned v;
            do {
                asm volatile("ld.acquire.gpu.global.u32 %0, [%1];" : "=r"(v) : "l"(barp));
            } while (v < tgt);
        }
        __syncthreads();
        ((float4*)hs)[tid]     = __ldcg(&d_hx4[((t+1)&1)*8192 + group*512 + tid]);
        ((float4*)hs)[tid+256] = __ldcg(&d_hx4[((t+1)&1)*8192 + group*512 + tid + 256]);
        __syncthreads();
    }
}

// ------------------- masked softmax + head mean + diag -------------------
__global__ void softmax_kernel(const int* __restrict__ l, float* __restrict__ ag) {
    int row = blockIdx.x; int b = row >> 9; int i = row & 511;
    int lb = l[b];
    float* out = ag + (long long)row*512;
    int tid = threadIdx.x;
    if (i >= lb) { out[tid] = 0.f; out[tid+256] = 0.f; return; }
    __shared__ float red[8];
    float a0 = 0.f, a1 = 0.f;
    int lane = tid & 31, wid = tid >> 5;
    for (int h = 0; h < 4; h++) {
        const float* sr = d_scores + ((long long)((b*4+h)*512 + i))*512;
        float v0 = (tid < lb)     ? sr[tid]     : -3.0e38f;
        float v1 = (tid+256 < lb) ? sr[tid+256] : -3.0e38f;
        float m = fmaxf(v0, v1);
        for (int o = 16; o; o >>= 1) m = fmaxf(m, __shfl_xor_sync(0xffffffffu, m, o));
        if (lane == 0) red[wid] = m;
        __syncthreads();
        m = red[0];
#pragma unroll
        for (int w = 1; w < 8; w++) m = fmaxf(m, red[w]);
        __syncthreads();
        float e0 = (tid < lb)     ? expf(v0 - m) : 0.f;
        float e1 = (tid+256 < lb) ? expf(v1 - m) : 0.f;
        float s = e0 + e1;
        for (int o = 16; o; o >>= 1) s += __shfl_xor_sync(0xffffffffu, s, o);
        if (lane == 0) red[wid] = s;
        __syncthreads();
        s = 0.f;
#pragma unroll
        for (int w = 0; w < 8; w++) s += red[w];
        float inv = 1.f/s;
        a0 += e0*inv; a1 += e1*inv;
        __syncthreads();
    }
    a0 *= 0.25f; a1 *= 0.25f;
    if (tid == i) a0 = 1.f;
    if (tid+256 == i) a1 = 1.f;
    out[tid] = a0; out[tid+256] = a1;
}

// ------------- exact kk-th smallest nonzero via 4-pass radix select ----------
__global__ __launch_bounds__(1024) void kth_kernel(const float* __restrict__ ag) {
    __shared__ unsigned wh[32][256];
    __shared__ unsigned chist[256];
    __shared__ int s_k, s_rem; __shared__ unsigned s_pref;
    int b = blockIdx.x; int tid = threadIdx.x; int wid = tid >> 5;
    const float* f = ag + (long long)b*262144;
    for (int pass = 0; pass < 4; pass++) {
        int shift = 24 - 8*pass;
        for (int j = tid; j < 32*256; j += 1024) ((unsigned*)wh)[j] = 0u;
        __syncthreads();
        unsigned pref = (pass == 0) ? 0u : s_pref;
        unsigned prefHi = pref >> (shift+8);
        for (int j = tid; j < 262144; j += 1024) {
            unsigned ub = __float_as_uint(f[j]);
            if (ub != 0u) {
                if (pass == 0 || (ub >> (shift+8)) == prefHi)
                    atomicAdd(&wh[wid][(ub >> shift) & 255u], 1u);
            }
        }
        __syncthreads();
        if (tid < 256) {
            unsigned s = 0;
#pragma unroll
            for (int w = 0; w < 32; w++) s += wh[w][tid];
            chist[tid] = s;
        }
        __syncthreads();
        if (tid == 0) {
            if (pass == 0) {
                unsigned nnz = 0;
                for (int c = 0; c < 256; c++) nnz += chist[c];
                int kk = (int)floorf((float)((int)nnz - 512) * 0.3f);
                s_k = kk; s_rem = kk; s_pref = 0u;
            }
            if (s_k > 0) {
                int rem = s_rem; unsigned pf = s_pref;
                for (int c = 0; c < 256; c++) {
                    if ((int)chist[c] >= rem) { pf |= ((unsigned)c) << shift; break; }
                    rem -= (int)chist[c];
                }
                s_rem = rem; s_pref = pf;
            }
        }
        __syncthreads();
        if (s_k <= 0) break;
    }
    if (tid == 0) d_thre[b] = (s_k > 0) ? __uint_as_float(s_pref) : 0.f;
}

// ------------------- prune + ensemble + denom -------------------
__global__ void prune_kernel(const float* __restrict__ adj, float* __restrict__ ag) {
    int row = blockIdx.x; int b = row >> 9; int tid = threadIdx.x;
    float thre = d_thre[b];
    long long base = (long long)row*512;
    float s = 0.f;
#pragma unroll
    for (int u = 0; u < 2; u++) {
        int j = tid + u*256;
        float v = ag[base + j];
        v = (v <= thre) ? 0.f : v;
        ag[base + j] = v;
        float e = 0.5f*adj[base + j] + 0.5f*v;
        d_adjens[base + j] = e;
        s += e;
    }
    for (int o = 16; o; o >>= 1) s += __shfl_xor_sync(0xffffffffu, s, o);
    __shared__ float red[8];
    if ((tid & 31) == 0) red[tid >> 5] = s;
    __syncthreads();
    if (tid == 0) {
        float tot = 0.f;
#pragma unroll
        for (int w = 0; w < 8; w++) tot += red[w];
        d_denom[row] = tot + 1.f;
    }
}

// ------------------- host launcher -------------------
extern "C" void kernel_launch(void* const* d_in, const int* in_sizes, int n_in,
                              void* d_out, int out_size) {
    const float* adj    = (const float*)d_in[0];
    const int*   tok    = (const int*)d_in[1];
    const int*   pos    = (const int*)d_in[2];
    const int*   post   = (const int*)d_in[3];
    const int*   l      = (const int*)d_in[4];
    const float* emb    = (const float*)d_in[5];
    const float* pose   = (const float*)d_in[6];
    const float* poste  = (const float*)d_in[7];
    const float* Wih_f  = (const float*)d_in[8];
    const float* Whh_f  = (const float*)d_in[9];
    const float* bih_f  = (const float*)d_in[10];
    const float* bhh_f  = (const float*)d_in[11];
    const float* Wih_b  = (const float*)d_in[12];
    const float* Whh_b  = (const float*)d_in[13];
    const float* bih_b  = (const float*)d_in[14];
    const float* bhh_b  = (const float*)d_in[15];
    const float* Wq     = (const float*)d_in[16];
    const float* bq     = (const float*)d_in[17];
    const float* Wk     = (const float*)d_in[18];
    const float* bk     = (const float*)d_in[19];
    const float* W0     = (const float*)d_in[20];
    const float* b0     = (const float*)d_in[21];
    const float* W1     = (const float*)d_in[22];
    const float* b1     = (const float*)d_in[23];

    float* xo = (float*)d_out;                      // [B,S,256]
    float* ag = xo + 8388608;                       // [B,S,S]
    float* go = xo + 25165824;                      // [B,S,512]

    void *pv;
    cudaGetSymbolAddress(&pv, d_embs);   float* embs   = (float*)pv;
    cudaGetSymbolAddress(&pv, d_Xf);     float* Xf     = (float*)pv;
    cudaGetSymbolAddress(&pv, d_Xb);     float* Xb     = (float*)pv;
    cudaGetSymbolAddress(&pv, d_q);      float* qb     = (float*)pv;
    cudaGetSymbolAddress(&pv, d_k);      float* kb     = (float*)pv;
    cudaGetSymbolAddress(&pv, d_scores); float* sc     = (float*)pv;
    cudaGetSymbolAddress(&pv, d_adjens); float* ens    = (float*)pv;
    cudaGetSymbolAddress(&pv, d_tb);     float* tbuf   = (float*)pv;
    cudaGetSymbolAddress(&pv, d_x1);     float* x1     = (float*)pv;
    cudaGetSymbolAddress(&pv, d_denom);  float* den    = (float*)pv;
    cudaGetSymbolAddress(&pv, d_biasf);  float* biasf  = (float*)pv;
    cudaGetSymbolAddress(&pv, d_biasb);  float* biasb  = (float*)pv;

    cudaMemsetAsync(go, 0, (size_t)NROWS*512*sizeof(float));
    prep_kernel<<<4,256>>>(bih_f, bhh_f, bih_b, bhh_b);
    init_kernel<<<16,1024>>>();
    sort_kernel<<<1,64>>>(l);
    embed_kernel<<<32768,128>>>(tok, pos, post, emb, pose, poste);

    // X = embs @ Wih^T + bias   [32768,1024]  (skip row tiles beyond l[b])
    mma_nt<<<dim3(8,256,1),256>>>(embs,360,0,0, Wih_f,360,0,0, Xf,1024,0,0,
                                  1,360,1.f, biasf, nullptr, 0, l, 0);
    mma_nt<<<dim3(8,256,1),256>>>(embs,360,0,0, Wih_b,360,0,0, Xb,1024,0,0,
                                  1,360,1.f, biasb, nullptr, 0, l, 0);

    cudaFuncSetAttribute(lstm_kernel, cudaFuncAttributeMaxDynamicSharedMemorySize, 36096*4);
    lstm_kernel<<<128,256,36096*4>>>(Whh_f, Whh_b, l, go);

    // q, k (skip row tiles beyond l[b])
    mma_nt<<<dim3(4,256,1),256>>>(go,512,0,0, Wq,512,0,0, qb,512,0,0,
                                  1,512,1.f, bq, nullptr, 0, l, 0);
    mma_nt<<<dim3(4,256,1),256>>>(go,512,0,0, Wk,512,0,0, kb,512,0,0,
                                  1,512,1.f, bk, nullptr, 0, l, 0);
    // scores[b,h] = q_bh @ k_bh^T / sqrt(128)  (skip row AND col tiles >= l[b])
    float alpha = 1.f/sqrtf(128.f);
    mma_nt<<<dim3(4,4,256),256>>>(qb,512, 262144,128, kb,512, 262144,128,
                                  sc,512, 1048576,262144, 4,128, alpha,
                                  nullptr, nullptr, 0, l, 1);
    softmax_kernel<<<32768,256>>>(l, ag);
    kth_kernel<<<64,1024>>>(ag);
    prune_kernel<<<32768,256>>>(adj, ag);

    // GCN layer 1: t = adjens @ g ; x1 = relu((t@W0^T+b0)/denom)
    cudaMemsetAsync(tbuf, 0, (size_t)16777216*sizeof(float));
    mma_nn<<<dim3(4,4,64),256>>>(ens,512,262144, go,512,262144, tbuf,512,262144, 512, l);
    mma_nt<<<dim3(2,256,1),256>>>(tbuf,512,0,0, W0,512,0,0, x1,256,0,0,
                                  1,512,1.f, b0, den, 1, nullptr, 0);
    // GCN layer 2: t2 = adjens @ x1 ; x = relu((t2@W1^T+b1)/denom)
    cudaMemsetAsync(tbuf, 0, (size_t)8388608*sizeof(float));
    mma_nn<<<dim3(2,4,64),256>>>(ens,512,262144, x1,256,131072, tbuf,256,131072, 512, l);
    mma_nt<<<dim3(2,256,1),256>>>(tbuf,256,0,0, W1,256,0,0, xo,256,0,0,
                                  1,256,1.f, b1, den, 1, nullptr, 0);
    (void)in_sizes; (void)n_in; (void)out_size;
}

// round 11
// speedup vs baseline: 1.1330x; 1.0045x over previous
#include <cuda_runtime.h>
#include <math.h>

#define SS 512
#define NROWS 32768LL

// ------------------- device scratch (no allocs allowed) -------------------
__device__ float d_embs[32768*360];
__device__ float d_Xf[32768*1024];
__device__ float d_Xb[32768*1024];
__device__ float d_q[32768*512];
__device__ float d_k[32768*512];
__device__ float d_scores[67108864];
__device__ float d_adjens[16777216];
__device__ float d_tb[16777216];
__device__ float d_x1[8388608];
__device__ float d_denom[32768];
__device__ float d_thre[64];
__device__ float d_biasf[1024];
__device__ float d_biasb[1024];
__device__ float4 d_hx4[2*16*512];
__device__ unsigned d_barc[16];
__device__ int d_perm[64];

// ------------------- small prep kernels -------------------
__global__ void prep_kernel(const float* bihf, const float* bhhf,
                            const float* bihb, const float* bhhb) {
    int i = blockIdx.x*blockDim.x + threadIdx.x;
    if (i < 1024) { d_biasf[i] = bihf[i]+bhhf[i]; d_biasb[i] = bihb[i]+bhhb[i]; }
}

__global__ void init_kernel() {
    int i = blockIdx.x*blockDim.x + threadIdx.x;
    if (i < 16) d_barc[i] = 0u;
    float4 z = make_float4(0.f,0.f,0.f,0.f);
    for (int j = i; j < 2*16*512; j += blockDim.x*gridDim.x) d_hx4[j] = z;
}

// rank-sort 64 lengths ascending -> d_perm (stable)
__global__ void sort_kernel(const int* __restrict__ l) {
    int i = threadIdx.x;
    int li = l[i]; int r = 0;
    for (int j = 0; j < 64; j++) {
        int lj = l[j];
        r += (lj < li) || (lj == li && j < i);
    }
    d_perm[r] = i;
}

__global__ void embed_kernel(const int* __restrict__ tok, const int* __restrict__ pos,
                             const int* __restrict__ post, const float* __restrict__ emb,
                             const float* __restrict__ pose, const float* __restrict__ poste) {
    int r = blockIdx.x;
    int t = tok[r], p = pos[r], q = post[r];
    float* o = d_embs + (long long)r*360;
    for (int d = threadIdx.x; d < 360; d += blockDim.x) {
        float v;
        if (d < 300)      v = emb[(long long)t*300 + d];
        else if (d < 330) v = pose[p*30 + (d-300)];
        else              v = poste[q*30 + (d-330)];
        o[d] = v;
    }
}

// ------------------- tf32 helpers -------------------
__device__ __forceinline__ unsigned f2tf(float x) {
    unsigned r; asm("cvt.rna.tf32.f32 %0, %1;" : "=r"(r) : "f"(x)); return r;
}
__device__ __forceinline__ void split8(float4 p0, float4 p1,
                                       unsigned* bg, unsigned* sv) {
    float v[8] = {p0.x,p0.y,p0.z,p0.w,p1.x,p1.y,p1.z,p1.w};
#pragma unroll
    for (int i = 0; i < 8; i++) {
        unsigned b = f2tf(v[i]);
        bg[i] = b;
        sv[i] = f2tf(v[i] - __uint_as_float(b));
    }
}

#define MMA_TF32(c, a, b)                                                   \
    asm volatile("mma.sync.aligned.m16n8k8.row.col.f32.tf32.tf32.f32 "      \
        "{%0,%1,%2,%3},{%4,%5,%6,%7},{%8,%9},{%0,%1,%2,%3};"                \
        : "+f"((c)[0]), "+f"((c)[1]), "+f"((c)[2]), "+f"((c)[3])            \
        : "r"((a)[0]), "r"((a)[1]), "r"((a)[2]), "r"((a)[3]),               \
          "r"((b)[0]), "r"((b)[1]))

#define FRAG_LOADS(cur)                                                     \
    unsigned ab[4][4], asx[4][4], bbf[4][2], bsf[4][2];                     \
    _Pragma("unroll")                                                       \
    for (int mt = 0; mt < 4; mt++) {                                        \
        int rr = wr + mt*16 + g;                                            \
        ab[mt][0]  = sAb[cur][rr][t4];   ab[mt][1]  = sAb[cur][rr+8][t4];   \
        ab[mt][2]  = sAb[cur][rr][t4+4]; ab[mt][3]  = sAb[cur][rr+8][t4+4]; \
        asx[mt][0] = sAs[cur][rr][t4];   asx[mt][1] = sAs[cur][rr+8][t4];   \
        asx[mt][2] = sAs[cur][rr][t4+4]; asx[mt][3] = sAs[cur][rr+8][t4+4]; \
    }                                                                       \
    _Pragma("unroll")                                                       \
    for (int nt = 0; nt < 4; nt++) {                                        \
        int cc = wc + nt*8 + g;                                             \
        bbf[nt][0] = sBb[cur][t4][cc];   bbf[nt][1] = sBb[cur][t4+4][cc];   \
        bsf[nt][0] = sBs[cur][t4][cc];   bsf[nt][1] = sBs[cur][t4+4][cc];   \
    }                                                                       \
    _Pragma("unroll")                                                       \
    for (int mt = 0; mt < 4; mt++)                                          \
        _Pragma("unroll")                                                   \
        for (int nt = 0; nt < 4; nt++) {                                    \
            MMA_TF32(c[mt][nt], ab[mt], bbf[nt]);                           \
            MMA_TF32(c[mt][nt], ab[mt], bsf[nt]);                           \
            MMA_TF32(c[mt][nt], asx[mt], bbf[nt]);                          \
        }

// ------------------- tf32 MMA GEMM NT (3xTF32, fp32-accurate):
// C = alpha*A[M,K]@B[N,K]^T (+bias)(/denom)(relu), with optional length-skip.
__global__ __launch_bounds__(256,1) void mma_nt(
    const float* __restrict__ A, int lda, long long sAo, long long sAi,
    const float* __restrict__ B, int ldb, long long sBo, long long sBi,
    float* __restrict__ C, int ldc, long long sCo, long long sCi,
    int innerZ, int K, float alpha,
    const float* __restrict__ bias, const float* __restrict__ denom, int relu,
    const int* __restrict__ lens, int colskip)
{
    int z = blockIdx.z; int zo = z / innerZ; int zi = z - zo*innerZ;
    if (lens) {
        int rowg = blockIdx.y*128;
        int bsm = (innerZ > 1) ? zo : (rowg >> 9);
        int lb = lens[bsm];
        int rloc = (innerZ > 1) ? rowg : (rowg & 511);
        if (rloc >= lb) return;
        if (colskip && blockIdx.x*128 >= lb) return;
    }
    A += zo*sAo + zi*sAi; B += zo*sBo + zi*sBi; C += zo*sCo + zi*sCi;
    __shared__ unsigned sAb[2][128][12], sAs[2][128][12];
    __shared__ unsigned sBb[2][8][132],  sBs[2][8][132];
    int tid = threadIdx.x; int r = tid & 127;
    bool isA = tid < 128;
    const float* G = isA ? (A + (long long)(blockIdx.y*128 + r)*lda)
                         : (B + (long long)(blockIdx.x*128 + r)*ldb);
    {
        float4 p0 = *(const float4*)G;
        float4 p1 = *(const float4*)(G + 4);
        unsigned bg[8], sv[8]; split8(p0, p1, bg, sv);
        if (isA) {
#pragma unroll
            for (int i = 0; i < 8; i++) { sAb[0][r][i] = bg[i]; sAs[0][r][i] = sv[i]; }
        } else {
#pragma unroll
            for (int i = 0; i < 8; i++) { sBb[0][i][r] = bg[i]; sBs[0][i][r] = sv[i]; }
        }
    }
    __syncthreads();
    int warp = tid >> 5, lane = tid & 31, g = lane >> 2, t4 = lane & 3;
    int wr = (warp >> 2) * 64, wc = (warp & 3) * 32;
    float c[4][4][4];
#pragma unroll
    for (int i = 0; i < 4; i++)
#pragma unroll
        for (int j = 0; j < 4; j++)
#pragma unroll
            for (int k = 0; k < 4; k++) c[i][j][k] = 0.f;
    int KT = K >> 3;
    for (int kt = 0; kt < KT; kt++) {
        int cur = kt & 1;
        float4 p0, p1;
        bool more = (kt + 1 < KT);
        if (more) {
            p0 = *(const float4*)(G + (kt+1)*8);
            p1 = *(const float4*)(G + (kt+1)*8 + 4);
        }
        FRAG_LOADS(cur);
        if (more) {
            unsigned bg[8], sv[8]; split8(p0, p1, bg, sv);
            int nx = (kt + 1) & 1;
            if (isA) {
#pragma unroll
                for (int i = 0; i < 8; i++) { sAb[nx][r][i] = bg[i]; sAs[nx][r][i] = sv[i]; }
            } else {
#pragma unroll
                for (int i = 0; i < 8; i++) { sBb[nx][i][r] = bg[i]; sBs[nx][i][r] = sv[i]; }
            }
            __syncthreads();
        }
    }
#pragma unroll
    for (int mt = 0; mt < 4; mt++)
#pragma unroll
        for (int nt = 0; nt < 4; nt++) {
            int row0 = blockIdx.y*128 + wr + mt*16 + g;
            int col0 = blockIdx.x*128 + wc + nt*8 + t4*2;
            float rd0 = denom ? (1.0f/denom[row0])   : 1.0f;
            float rd1 = denom ? (1.0f/denom[row0+8]) : 1.0f;
            float b0v = bias ? bias[col0]   : 0.f;
            float b1v = bias ? bias[col0+1] : 0.f;
            float v00 = (c[mt][nt][0]*alpha + b0v) * rd0;
            float v01 = (c[mt][nt][1]*alpha + b1v) * rd0;
            float v10 = (c[mt][nt][2]*alpha + b0v) * rd1;
            float v11 = (c[mt][nt][3]*alpha + b1v) * rd1;
            if (relu) {
                v00 = fmaxf(v00, 0.f); v01 = fmaxf(v01, 0.f);
                v10 = fmaxf(v10, 0.f); v11 = fmaxf(v11, 0.f);
            }
            *(float2*)&C[(long long)row0*ldc + col0]     = make_float2(v00, v01);
            *(float2*)&C[(long long)(row0+8)*ldc + col0] = make_float2(v10, v11);
        }
}

// ------------------- tf32 MMA GEMM NN (batched, 3xTF32): C = A[M,K]@B[K,N]
// lens: per-z sample length; skip row tiles >= l (C pre-zeroed) and clamp K.
__global__ __launch_bounds__(256,1) void mma_nn(
    const float* __restrict__ A, int lda, long long sA,
    const float* __restrict__ B, int ldb, long long sB,
    float* __restrict__ C, int ldc, long long sC, int K,
    const int* __restrict__ lens)
{
    int z = blockIdx.z;
    if (lens) {
        int lb = lens[z];
        if (blockIdx.y*128 >= lb) return;
        int Keff = ((lb + 7) >> 3) << 3;
        if (Keff < K) K = Keff;
    }
    A += (long long)z*sA; B += (long long)z*sB; C += (long long)z*sC;
    __shared__ unsigned sAb[2][128][12], sAs[2][128][12];
    __shared__ unsigned sBb[2][8][132],  sBs[2][8][132];
    int tid = threadIdx.x; int r = tid & 127;
    bool isA = tid < 128;
    const float* G;
    int kRow = 0, cB = 0;
    if (isA) {
        G = A + (long long)(blockIdx.y*128 + r)*lda;
    } else {
        kRow = r >> 4; cB = (r & 15) * 8;
        G = B + (long long)kRow*ldb + blockIdx.x*128 + cB;
    }
    {
        float4 p0 = *(const float4*)G;
        float4 p1 = *(const float4*)(G + 4);
        unsigned bg[8], sv[8]; split8(p0, p1, bg, sv);
        if (isA) {
#pragma unroll
            for (int i = 0; i < 8; i++) { sAb[0][r][i] = bg[i]; sAs[0][r][i] = sv[i]; }
        } else {
#pragma unroll
            for (int i = 0; i < 8; i++) { sBb[0][kRow][cB+i] = bg[i]; sBs[0][kRow][cB+i] = sv[i]; }
        }
    }
    __syncthreads();
    int warp = tid >> 5, lane = tid & 31, g = lane >> 2, t4 = lane & 3;
    int wr = (warp >> 2) * 64, wc = (warp & 3) * 32;
    float c[4][4][4];
#pragma unroll
    for (int i = 0; i < 4; i++)
#pragma unroll
        for (int j = 0; j < 4; j++)
#pragma unroll
            for (int k = 0; k < 4; k++) c[i][j][k] = 0.f;
    int KT = K >> 3;
    for (int kt = 0; kt < KT; kt++) {
        int cur = kt & 1;
        float4 p0, p1;
        bool more = (kt + 1 < KT);
        if (more) {
            if (isA) {
                p0 = *(const float4*)(G + (kt+1)*8);
                p1 = *(const float4*)(G + (kt+1)*8 + 4);
            } else {
                p0 = *(const float4*)(G + (long long)(kt+1)*8*ldb);
                p1 = *(const float4*)(G + (long long)(kt+1)*8*ldb + 4);
            }
        }
        FRAG_LOADS(cur);
        if (more) {
            unsigned bg[8], sv[8]; split8(p0, p1, bg, sv);
            int nx = (kt + 1) & 1;
            if (isA) {
#pragma unroll
                for (int i = 0; i < 8; i++) { sAb[nx][r][i] = bg[i]; sAs[nx][r][i] = sv[i]; }
            } else {
#pragma unroll
                for (int i = 0; i < 8; i++) { sBb[nx][kRow][cB+i] = bg[i]; sBs[nx][kRow][cB+i] = sv[i]; }
            }
            __syncthreads();
        }
    }
#pragma unroll
    for (int mt = 0; mt < 4; mt++)
#pragma unroll
        for (int nt = 0; nt < 4; nt++) {
            int row0 = blockIdx.y*128 + wr + mt*16 + g;
            int col0 = blockIdx.x*128 + wc + nt*8 + t4*2;
            *(float2*)&C[(long long)row0*ldc + col0]     = make_float2(c[mt][nt][0], c[mt][nt][1]);
            *(float2*)&C[(long long)(row0+8)*ldc + col0] = make_float2(c[mt][nt][2], c[mt][nt][3]);
        }
}

// ------------------- f32x2 helpers (sm_100a packed FMA) -------------------
__device__ __forceinline__ unsigned long long pk2(float lo, float hi) {
    unsigned long long r; asm("mov.b64 %0, {%1,%2};" : "=l"(r) : "f"(lo), "f"(hi)); return r;
}
__device__ __forceinline__ unsigned long long dup2(float x) {
    unsigned long long r; asm("mov.b64 %0, {%1,%1};" : "=l"(r) : "f"(x)); return r;
}
#define FMA2(acc, a, b) asm("fma.rn.f32x2 %0, %1, %2, %0;" : "+l"(acc) : "l"(a), "l"(b))

// ------------------- BiLSTM recurrence (FFMA2 pipe, paired-h layout) -------
// 128 blocks = 16 groups(8 length-sorted samples x dir) x 8 j-split, 256 thr.
// h buffers (smem + d_hx4) hold pairs interleaved: [pair][k][2].
__global__ __launch_bounds__(256) void lstm_kernel(
    const float* __restrict__ Whhf, const float* __restrict__ Whhb,
    const int* __restrict__ l, float* __restrict__ gout)
{
    extern __shared__ float sm[];
    float* Ws = sm;
    float* hs = sm + 32768;
    float* gs = hs + 2048;
    float* cs = gs + 1024;
    int bid = blockIdx.x; int group = bid >> 3; int q = bid & 7;
    int dir = group >> 3; int sg = group & 7;
    int tid = threadIdx.x;
    const float* Whh = dir ? Whhb : Whhf;
    const float* Xd = dir ? d_Xb : d_Xf;
    unsigned* barp = &d_barc[group];
    for (int idx = tid; idx < 32768; idx += 256) {
        int rr = idx >> 8; int kk = idx & 255;
        int gr = ((rr>>5)<<8) + (q<<5) + (rr&31);
        Ws[(((kk>>2)*128)+rr)*4 + (kk&3)] = Whh[gr*256 + kk];
    }
    cs[tid] = 0.f;
    for (int idx = tid; idx < 2048; idx += 256) hs[idx] = 0.f;
    int ln[8]; int smp[8]; int lmax = 0;
#pragma unroll
    for (int n = 0; n < 8; n++) {
        int s = d_perm[sg*8+n];
        smp[n] = s; ln[n] = l[s];
        lmax = max(lmax, ln[n]);
    }
    int slot = tid >> 7; int r = tid & 127;
    int n0 = slot*4;
    int p0 = slot*2;                 // pair base: pairs p0, p0+1 (samples n0..n0+3)
    int grow = ((r>>5)<<8) + (q<<5) + (r&31);
    __syncthreads();
    const float4* Ws4 = (const float4*)Ws;

    float xr0=0.f, xr1=0.f, xr2=0.f, xr3=0.f;
    {
        if (0 < ln[n0+0]) { int tt = dir ? (ln[n0+0]-1) : 0; xr0 = Xd[((long long)(smp[n0+0]*SS+tt)<<10) + grow]; }
        if (0 < ln[n0+1]) { int tt = dir ? (ln[n0+1]-1) : 0; xr1 = Xd[((long long)(smp[n0+1]*SS+tt)<<10) + grow]; }
        if (0 < ln[n0+2]) { int tt = dir ? (ln[n0+2]-1) : 0; xr2 = Xd[((long long)(smp[n0+2]*SS+tt)<<10) + grow]; }
        if (0 < ln[n0+3]) { int tt = dir ? (ln[n0+3]-1) : 0; xr3 = Xd[((long long)(smp[n0+3]*SS+tt)<<10) + grow]; }
    }

    for (int t = 0; t < lmax; t++) {
        unsigned long long accA = pk2(xr0, xr1);
        unsigned long long accB = pk2(xr2, xr3);
        const ulonglong2* hpA = (const ulonglong2*)(hs + p0*512);
        const ulonglong2* hpB = (const ulonglong2*)(hs + (p0+1)*512);
#pragma unroll 8
        for (int k4 = 0; k4 < 64; k4++) {
            float4 w = Ws4[k4*128 + r];
            ulonglong2 U0 = hpA[k4*2], U1 = hpA[k4*2+1];
            ulonglong2 V0 = hpB[k4*2], V1 = hpB[k4*2+1];
            unsigned long long wx = dup2(w.x), wy = dup2(w.y);
            unsigned long long wz = dup2(w.z), ww = dup2(w.w);
            FMA2(accA, wx, U0.x); FMA2(accB, wx, V0.x);
            FMA2(accA, wy, U0.y); FMA2(accB, wy, V0.y);
            FMA2(accA, wz, U1.x); FMA2(accB, wz, V1.x);
            FMA2(accA, ww, U1.y); FMA2(accB, ww, V1.y);
        }
        float acc0, acc1, acc2, acc3;
        asm("mov.b64 {%0,%1}, %2;" : "=f"(acc0), "=f"(acc1) : "l"(accA));
        asm("mov.b64 {%0,%1}, %2;" : "=f"(acc2), "=f"(acc3) : "l"(accB));
        gs[(n0+0)*128 + r] = acc0;
        gs[(n0+1)*128 + r] = acc1;
        gs[(n0+2)*128 + r] = acc2;
        gs[(n0+3)*128 + r] = acc3;
        __syncthreads();
        {
            int n = tid >> 5, jl = tid & 31;
            if (t < ln[n]) {
                float gi = gs[n*128+jl], gf = gs[n*128+32+jl];
                float gg = gs[n*128+64+jl], go_ = gs[n*128+96+jl];
                float c = cs[n*32+jl];
                c = (1.f/(1.f+expf(-gf)))*c + (1.f/(1.f+expf(-gi)))*tanhf(gg);
                float h = (1.f/(1.f+expf(-go_)))*tanhf(c);
                cs[n*32+jl] = c;
                float* dst = (float*)&d_hx4[((t+1)&1)*8192 + group*512];
                int hidx = q*32 + jl;
                __stcg(dst + (n>>1)*512 + hidx*2 + (n&1), h);
                int bsm = smp[n];
                int tpos = dir ? (ln[n]-1-t) : t;
                gout[((long long)(bsm*SS+tpos))*512 + dir*256 + hidx] = h;
            }
        }
        if (t+1 == lmax) break;
        __syncthreads();
        if (tid == 0) {
            __threadfence();
            atomicAdd(barp, 1u);
        }
        int tn = t+1;
        xr0 = xr1 = xr2 = xr3 = 0.f;
        if (tn < ln[n0+0]) { int tt = dir ? (ln[n0+0]-1-tn) : tn; xr0 = Xd[((long long)(smp[n0+0]*SS+tt)<<10) + grow]; }
        if (tn < ln[n0+1]) { int tt = dir ? (ln[n0+1]-1-tn) : tn; xr1 = Xd[((long long)(smp[n0+1]*SS+tt)<<10) + grow]; }
        if (tn < ln[n0+2]) { int tt = dir ? (ln[n0+2]-1-tn) : tn; xr2 = Xd[((long long)(smp[n0+2]*SS+tt)<<10) + grow]; }
        if (tn < ln[n0+3]) { int tt = dir ? (ln[n0+3]-1-tn) : tn; xr3 = Xd[((long long)(smp[n0+3]*SS+tt)<<10) + grow]; }
        if (tid == 0) {
            unsigned tgt = (unsigned)(t+1)*8u;
            unsigned v;
            do {
                asm volatile("ld.acquire.gpu.global.u32 %0, [%1];" : "=r"(v) : "l"(barp));
            } while (v < tgt);
        }
        __syncthreads();
        ((float4*)hs)[tid]     = __ldcg(&d_hx4[((t+1)&1)*8192 + group*512 + tid]);
        ((float4*)hs)[tid+256] = __ldcg(&d_hx4[((t+1)&1)*8192 + group*512 + tid + 256]);
        __syncthreads();
    }
}

// ------------------- masked softmax + head mean + diag -------------------
__global__ void softmax_kernel(const int* __restrict__ l, float* __restrict__ ag) {
    int row = blockIdx.x; int b = row >> 9; int i = row & 511;
    int lb = l[b];
    float* out = ag + (long long)row*512;
    int tid = threadIdx.x;
    if (i >= lb) { out[tid] = 0.f; out[tid+256] = 0.f; return; }
    __shared__ float red[8];
    float a0 = 0.f, a1 = 0.f;
    int lane = tid & 31, wid = tid >> 5;
    for (int h = 0; h < 4; h++) {
        const float* sr = d_scores + ((long long)((b*4+h)*512 + i))*512;
        float v0 = (tid < lb)     ? sr[tid]     : -3.0e38f;
        float v1 = (tid+256 < lb) ? sr[tid+256] : -3.0e38f;
        float m = fmaxf(v0, v1);
        for (int o = 16; o; o >>= 1) m = fmaxf(m, __shfl_xor_sync(0xffffffffu, m, o));
        if (lane == 0) red[wid] = m;
        __syncthreads();
        m = red[0];
#pragma unroll
        for (int w = 1; w < 8; w++) m = fmaxf(m, red[w]);
        __syncthreads();
        float e0 = (tid < lb)     ? expf(v0 - m) : 0.f;
        float e1 = (tid+256 < lb) ? expf(v1 - m) : 0.f;
        float s = e0 + e1;
        for (int o = 16; o; o >>= 1) s += __shfl_xor_sync(0xffffffffu, s, o);
        if (lane == 0) red[wid] = s;
        __syncthreads();
        s = 0.f;
#pragma unroll
        for (int w = 0; w < 8; w++) s += red[w];
        float inv = 1.f/s;
        a0 += e0*inv; a1 += e1*inv;
        __syncthreads();
    }
    a0 *= 0.25f; a1 *= 0.25f;
    if (tid == i) a0 = 1.f;
    if (tid+256 == i) a1 = 1.f;
    out[tid] = a0; out[tid+256] = a1;
}

// ------------- exact kk-th smallest nonzero via 4-pass radix select ----------
__global__ __launch_bounds__(1024) void kth_kernel(const float* __restrict__ ag) {
    __shared__ unsigned wh[32][256];
    __shared__ unsigned chist[256];
    __shared__ int s_k, s_rem; __shared__ unsigned s_pref;
    int b = blockIdx.x; int tid = threadIdx.x; int wid = tid >> 5;
    const float* f = ag + (long long)b*262144;
    for (int pass = 0; pass < 4; pass++) {
        int shift = 24 - 8*pass;
        for (int j = tid; j < 32*256; j += 1024) ((unsigned*)wh)[j] = 0u;
        __syncthreads();
        unsigned pref = (pass == 0) ? 0u : s_pref;
        unsigned prefHi = pref >> (shift+8);
        for (int j = tid; j < 262144; j += 1024) {
            unsigned ub = __float_as_uint(f[j]);
            if (ub != 0u) {
                if (pass == 0 || (ub >> (shift+8)) == prefHi)
                    atomicAdd(&wh[wid][(ub >> shift) & 255u], 1u);
            }
        }
        __syncthreads();
        if (tid < 256) {
            unsigned s = 0;
#pragma unroll
            for (int w = 0; w < 32; w++) s += wh[w][tid];
            chist[tid] = s;
        }
        __syncthreads();
        if (tid == 0) {
            if (pass == 0) {
                unsigned nnz = 0;
                for (int c = 0; c < 256; c++) nnz += chist[c];
                int kk = (int)floorf((float)((int)nnz - 512) * 0.3f);
                s_k = kk; s_rem = kk; s_pref = 0u;
            }
            if (s_k > 0) {
                int rem = s_rem; unsigned pf = s_pref;
                for (int c = 0; c < 256; c++) {
                    if ((int)chist[c] >= rem) { pf |= ((unsigned)c) << shift; break; }
                    rem -= (int)chist[c];
                }
                s_rem = rem; s_pref = pf;
            }
        }
        __syncthreads();
        if (s_k <= 0) break;
    }
    if (tid == 0) d_thre[b] = (s_k > 0) ? __uint_as_float(s_pref) : 0.f;
}

// ------------------- prune + ensemble + denom -------------------
__global__ void prune_kernel(const float* __restrict__ adj, float* __restrict__ ag) {
    int row = blockIdx.x; int b = row >> 9; int tid = threadIdx.x;
    float thre = d_thre[b];
    long long base = (long long)row*512;
    float s = 0.f;
#pragma unroll
    for (int u = 0; u < 2; u++) {
        int j = tid + u*256;
        float v = ag[base + j];
        v = (v <= thre) ? 0.f : v;
        ag[base + j] = v;
        float e = 0.5f*adj[base + j] + 0.5f*v;
        d_adjens[base + j] = e;
        s += e;
    }
    for (int o = 16; o; o >>= 1) s += __shfl_xor_sync(0xffffffffu, s, o);
    __shared__ float red[8];
    if ((tid & 31) == 0) red[tid >> 5] = s;
    __syncthreads();
    if (tid == 0) {
        float tot = 0.f;
#pragma unroll
        for (int w = 0; w < 8; w++) tot += red[w];
        d_denom[row] = tot + 1.f;
    }
}

// ------------------- host launcher -------------------
extern "C" void kernel_launch(void* const* d_in, const int* in_sizes, int n_in,
                              void* d_out, int out_size) {
    const float* adj    = (const float*)d_in[0];
    const int*   tok    = (const int*)d_in[1];
    const int*   pos    = (const int*)d_in[2];
    const int*   post   = (const int*)d_in[3];
    const int*   l      = (const int*)d_in[4];
    const float* emb    = (const float*)d_in[5];
    const float* pose   = (const float*)d_in[6];
    const float* poste  = (const float*)d_in[7];
    const float* Wih_f  = (const float*)d_in[8];
    const float* Whh_f  = (const float*)d_in[9];
    const float* bih_f  = (const float*)d_in[10];
    const float* bhh_f  = (const float*)d_in[11];
    const float* Wih_b  = (const float*)d_in[12];
    const float* Whh_b  = (const float*)d_in[13];
    const float* bih_b  = (const float*)d_in[14];
    const float* bhh_b  = (const float*)d_in[15];
    const float* Wq     = (const float*)d_in[16];
    const float* bq     = (const float*)d_in[17];
    const float* Wk     = (const float*)d_in[18];
    const float* bk     = (const float*)d_in[19];
    const float* W0     = (const float*)d_in[20];
    const float* b0     = (const float*)d_in[21];
    const float* W1     = (const float*)d_in[22];
    const float* b1     = (const float*)d_in[23];

    float* xo = (float*)d_out;                      // [B,S,256]
    float* ag = xo + 8388608;                       // [B,S,S]
    float* go = xo + 25165824;                      // [B,S,512]

    void *pv;
    cudaGetSymbolAddress(&pv, d_embs);   float* embs   = (float*)pv;
    cudaGetSymbolAddress(&pv, d_Xf);     float* Xf     = (float*)pv;
    cudaGetSymbolAddress(&pv, d_Xb);     float* Xb     = (float*)pv;
    cudaGetSymbolAddress(&pv, d_q);      float* qb     = (float*)pv;
    cudaGetSymbolAddress(&pv, d_k);      float* kb     = (float*)pv;
    cudaGetSymbolAddress(&pv, d_scores); float* sc     = (float*)pv;
    cudaGetSymbolAddress(&pv, d_adjens); float* ens    = (float*)pv;
    cudaGetSymbolAddress(&pv, d_tb);     float* tbuf   = (float*)pv;
    cudaGetSymbolAddress(&pv, d_x1);     float* x1     = (float*)pv;
    cudaGetSymbolAddress(&pv, d_denom);  float* den    = (float*)pv;
    cudaGetSymbolAddress(&pv, d_biasf);  float* biasf  = (float*)pv;
    cudaGetSymbolAddress(&pv, d_biasb);  float* biasb  = (float*)pv;

    cudaMemsetAsync(go, 0, (size_t)NROWS*512*sizeof(float));
    prep_kernel<<<4,256>>>(bih_f, bhh_f, bih_b, bhh_b);
    init_kernel<<<16,1024>>>();
    sort_kernel<<<1,64>>>(l);
    embed_kernel<<<32768,128>>>(tok, pos, post, emb, pose, poste);

    // X = embs @ Wih^T + bias   [32768,1024]  (skip row tiles beyond l[b])
    mma_nt<<<dim3(8,256,1),256>>>(embs,360,0,0, Wih_f,360,0,0, Xf,1024,0,0,
                                  1,360,1.f, biasf, nullptr, 0, l, 0);
    mma_nt<<<dim3(8,256,1),256>>>(embs,360,0,0, Wih_b,360,0,0, Xb,1024,0,0,
                                  1,360,1.f, biasb, nullptr, 0, l, 0);

    cudaFuncSetAttribute(lstm_kernel, cudaFuncAttributeMaxDynamicSharedMemorySize, 36096*4);
    lstm_kernel<<<128,256,36096*4>>>(Whh_f, Whh_b, l, go);

    // q, k (skip row tiles beyond l[b])
    mma_nt<<<dim3(4,256,1),256>>>(go,512,0,0, Wq,512,0,0, qb,512,0,0,
                                  1,512,1.f, bq, nullptr, 0, l, 0);
    mma_nt<<<dim3(4,256,1),256>>>(go,512,0,0, Wk,512,0,0, kb,512,0,0,
                                  1,512,1.f, bk, nullptr, 0, l, 0);
    // scores[b,h] = q_bh @ k_bh^T / sqrt(128)  (skip row AND col tiles >= l[b])
    float alpha = 1.f/sqrtf(128.f);
    mma_nt<<<dim3(4,4,256),256>>>(qb,512, 262144,128, kb,512, 262144,128,
                                  sc,512, 1048576,262144, 4,128, alpha,
                                  nullptr, nullptr, 0, l, 1);
    softmax_kernel<<<32768,256>>>(l, ag);
    kth_kernel<<<64,1024>>>(ag);
    prune_kernel<<<32768,256>>>(adj, ag);

    // GCN layer 1: t = adjens @ g ; x1 = relu((t@W0^T+b0)/denom)
    cudaMemsetAsync(tbuf, 0, (size_t)16777216*sizeof(float));
    mma_nn<<<dim3(4,4,64),256>>>(ens,512,262144, go,512,262144, tbuf,512,262144, 512, l);
    mma_nt<<<dim3(2,256,1),256>>>(tbuf,512,0,0, W0,512,0,0, x1,256,0,0,
                                  1,512,1.f, b0, den, 1, nullptr, 0);
    // GCN layer 2: t2 = adjens @ x1 ; x = relu((t2@W1^T+b1)/denom)
    cudaMemsetAsync(tbuf, 0, (size_t)8388608*sizeof(float));
    mma_nn<<<dim3(2,4,64),256>>>(ens,512,262144, x1,256,131072, tbuf,256,131072, 512, l);
    mma_nt<<<dim3(2,256,1),256>>>(tbuf,256,0,0, W1,256,0,0, xo,256,0,0,
                                  1,256,1.f, b1, den, 1, nullptr, 0);
    (void)in_sizes; (void)n_in; (void)out_size;
}